// round 10
// baseline (speedup 1.0000x reference)
#include <cuda_runtime.h>
#include <cuda_bf16.h>
#include <math.h>

// ---------------------------------------------------------------------------
// Problem constants
// ---------------------------------------------------------------------------
#define BATCH 256
#define TLEN  512
#define DIN   64
#define HID   128
#define G4    512              // 4*H
#define NCLS  12
#define MROWS (BATCH * TLEN)   // 131072

typedef unsigned long long ull;

// ---- helpers ----
__device__ __forceinline__ unsigned cvt_tf32(float x) {
    unsigned u; asm("cvt.rna.tf32.f32 %0, %1;" : "=r"(u) : "f"(x)); return u;
}
__device__ __forceinline__ void mma_tf32(float d[4], const unsigned a[4],
                                         unsigned b0, unsigned b1) {
    asm("mma.sync.aligned.m16n8k8.row.col.f32.tf32.tf32.f32 "
        "{%0,%1,%2,%3},{%4,%5,%6,%7},{%8,%9},{%0,%1,%2,%3};"
        : "+f"(d[0]), "+f"(d[1]), "+f"(d[2]), "+f"(d[3])
        : "r"(a[0]), "r"(a[1]), "r"(a[2]), "r"(a[3]), "r"(b0), "r"(b1));
}
// pack two f32 -> bf16x2 (low = first arg)
__device__ __forceinline__ unsigned pack_bf16(float lo, float hi) {
    unsigned r;
    asm("cvt.rn.bf16x2.f32 %0, %1, %2;" : "=r"(r) : "f"(hi), "f"(lo));
    return r;
}
__device__ __forceinline__ void mma_bf16(float d[4], const unsigned a[4],
                                         unsigned b0, unsigned b1) {
    asm("mma.sync.aligned.m16n8k16.row.col.f32.bf16.bf16.f32 "
        "{%0,%1,%2,%3},{%4,%5,%6,%7},{%8,%9},{%0,%1,%2,%3};"
        : "+f"(d[0]), "+f"(d[1]), "+f"(d[2]), "+f"(d[3])
        : "r"(a[0]), "r"(a[1]), "r"(a[2]), "r"(a[3]), "r"(b0), "r"(b1));
}
__device__ __forceinline__ float tanh_fast(float x) {
    float y; asm("tanh.approx.f32 %0, %1;" : "=f"(y) : "f"(x)); return y;
}
__device__ __forceinline__ float sigm_fast(float x) {
    return fmaf(0.5f, tanh_fast(0.5f * x), 0.5f);
}
__device__ __forceinline__ unsigned smem_u32(const void* p) {
    unsigned a;
    asm("{ .reg .u64 t; cvta.to.shared.u64 t, %1; cvt.u32.u64 %0, t; }"
        : "=r"(a) : "l"(p));
    return a;
}
// store u64 into peer CTA's smem (DSMEM)
__device__ __forceinline__ void st_cluster_u64(unsigned local_addr, unsigned peer,
                                               unsigned lo, unsigned hi) {
    unsigned ra; ull v;
    asm volatile("mapa.shared::cluster.u32 %0, %1, %2;"
                 : "=r"(ra) : "r"(local_addr), "r"(peer));
    asm("mov.b64 %0, {%1,%2};" : "=l"(v) : "r"(lo), "r"(hi));
    asm volatile("st.shared::cluster.u64 [%0], %1;" :: "r"(ra), "l"(v) : "memory");
}
__device__ __forceinline__ void mbar_init(unsigned addr, unsigned cnt) {
    asm volatile("mbarrier.init.shared.b64 [%0], %1;" :: "r"(addr), "r"(cnt) : "memory");
}
// cluster-scope RELEASE arrive on local CTA's barrier
__device__ __forceinline__ void mbar_arrive_local(unsigned addr) {
    asm volatile("mbarrier.arrive.release.cluster.shared::cta.b64 _, [%0];"
                 :: "r"(addr) : "memory");
}
// cluster-scope RELEASE arrive on peer CTA's barrier
__device__ __forceinline__ void mbar_arrive_remote(unsigned addr, unsigned peer) {
    asm volatile("{\n\t.reg .b32 ra;\n\t"
                 "mapa.shared::cluster.u32 ra, %0, %1;\n\t"
                 "mbarrier.arrive.release.cluster.shared::cluster.b64 _, [ra];\n\t}"
                 :: "r"(addr), "r"(peer) : "memory");
}
// cluster-scope ACQUIRE wait (pairs with remote release arrives)
__device__ __forceinline__ void mbar_wait(unsigned addr, unsigned parity) {
    unsigned done;
    asm volatile("{\n\t.reg .pred p;\n\t"
                 "mbarrier.try_wait.parity.acquire.cluster.shared::cta.b64 p, [%1], %2;\n\t"
                 "selp.b32 %0, 1, 0, p;\n\t}"
                 : "=r"(done) : "r"(addr), "r"(parity) : "memory");
    while (!done) {
        asm volatile("{\n\t.reg .pred p;\n\t"
                     "mbarrier.try_wait.parity.acquire.cluster.shared::cta.b64 p, [%1], %2, 0x989680;\n\t"
                     "selp.b32 %0, 1, 0, p;\n\t}"
                     : "=r"(done) : "r"(addr), "r"(parity) : "memory");
    }
}
#define CLUSTER_SYNC() do { \
    asm volatile("barrier.cluster.arrive.aligned;" ::: "memory"); \
    asm volatile("barrier.cluster.wait.aligned;"   ::: "memory"); \
} while (0)

// ---------------------------------------------------------------------------
// Scratch (device globals; allocation in kernel_launch is forbidden)
// ---------------------------------------------------------------------------
__device__ float g_G0[(size_t)2 * BATCH * TLEN * G4];   // layer0 gate pre-acts [dir][b][t][g]
__device__ float g_G1[(size_t)2 * BATCH * TLEN * G4];   // layer1 gate pre-acts
__device__ float g_H1[(size_t)BATCH * TLEN * 2 * HID];  // layer0 output [b][t][256]
__device__ float g_HT[(size_t)2 * BATCH * HID];         // layer1 final hidden [dir][b][128]

// ---------------------------------------------------------------------------
// Gate-input GEMM on tensor cores (tf32 mma.sync m16n8k8, "NT" layout).
//   Proven from R4: CTA tile 128x128, BK=32, 8 warps.
// ---------------------------------------------------------------------------
template <int KDIM>
__global__ __launch_bounds__(256, 2)
void gate_gemm_tc(const float* __restrict__ A,
                  const float* __restrict__ W,
                  const float* __restrict__ bias,
                  const int*   __restrict__ lens,
                  float*       __restrict__ G)
{
    constexpr int BM = 128, BN = 128, BK = 32, LDSA = BK + 4;   // 36
    __shared__ unsigned As[BM * LDSA];
    __shared__ unsigned Ws[BN * LDSA];

    const int m0 = blockIdx.y * BM;
    const int n0 = blockIdx.x * BN;
    const int b  = m0 >> 9;
    if ((m0 & 511) >= lens[b]) return;

    const int tid  = threadIdx.x;
    const int lane = tid & 31;
    const int w    = tid >> 5;
    const int g    = lane >> 2;
    const int t    = lane & 3;
    const int wm   = w >> 1;
    const int wn   = w & 1;

    const int lrow = tid >> 1;
    const int lcol = (tid & 1) * 16;

    float d[2][8][4];
#pragma unroll
    for (int mi = 0; mi < 2; mi++)
#pragma unroll
        for (int ni = 0; ni < 8; ni++)
#pragma unroll
            for (int c = 0; c < 4; c++) d[mi][ni][c] = 0.f;

    for (int k0 = 0; k0 < KDIM; k0 += BK) {
        float4 av[4], wv[4];
        const float* Ap = A + (size_t)(m0 + lrow) * KDIM + k0 + lcol;
        const float* Wp = W + (size_t)(n0 + lrow) * KDIM + k0 + lcol;
#pragma unroll
        for (int i = 0; i < 4; i++) {
            av[i] = *(const float4*)(Ap + 4 * i);
            wv[i] = *(const float4*)(Wp + 4 * i);
        }
        __syncthreads();
#pragma unroll
        for (int i = 0; i < 4; i++) {
            uint4 ua = { cvt_tf32(av[i].x), cvt_tf32(av[i].y),
                         cvt_tf32(av[i].z), cvt_tf32(av[i].w) };
            uint4 uw = { cvt_tf32(wv[i].x), cvt_tf32(wv[i].y),
                         cvt_tf32(wv[i].z), cvt_tf32(wv[i].w) };
            *(uint4*)&As[lrow * LDSA + lcol + 4 * i] = ua;
            *(uint4*)&Ws[lrow * LDSA + lcol + 4 * i] = uw;
        }
        __syncthreads();

#pragma unroll
        for (int kk = 0; kk < BK; kk += 8) {
            unsigned a[2][4];
#pragma unroll
            for (int mi = 0; mi < 2; mi++) {
                const int r = wm * 32 + mi * 16;
                a[mi][0] = As[(r + g)     * LDSA + kk + t];
                a[mi][1] = As[(r + g + 8) * LDSA + kk + t];
                a[mi][2] = As[(r + g)     * LDSA + kk + t + 4];
                a[mi][3] = As[(r + g + 8) * LDSA + kk + t + 4];
            }
#pragma unroll
            for (int ni = 0; ni < 8; ni++) {
                const int c = wn * 64 + ni * 8;
                const unsigned b0 = Ws[(c + g) * LDSA + kk + t];
                const unsigned b1 = Ws[(c + g) * LDSA + kk + t + 4];
                mma_tf32(d[0][ni], a[0], b0, b1);
                mma_tf32(d[1][ni], a[1], b0, b1);
            }
        }
    }

#pragma unroll
    for (int ni = 0; ni < 8; ni++) {
        const int col  = n0 + wn * 64 + ni * 8 + 2 * t;
        const int dirn = col >> 9;
        const int gg   = col & 511;
        const float2 bv = *(const float2*)(bias + col);
#pragma unroll
        for (int mi = 0; mi < 2; mi++) {
            const int m  = m0 + wm * 32 + mi * 16 + g;
            const int tt = m & 511;
            const size_t base = ((((size_t)dirn * BATCH + b) * TLEN) + tt) * G4 + gg;
            float2 v0 = { d[mi][ni][0] + bv.x, d[mi][ni][1] + bv.y };
            float2 v1 = { d[mi][ni][2] + bv.x, d[mi][ni][3] + bv.y };
            *(float2*)&G[base]                  = v0;   // row m
            *(float2*)&G[base + 8 * (size_t)G4] = v1;   // row m+8
        }
    }
}

// ---------------------------------------------------------------------------
// Tensor-core LSTM recurrence, 2-CTA cluster (unit-split).
//   Cluster = (dir, 16 batches); CTA rank r owns hidden units [64r, 64r+64).
//   64 CTAs, 256 threads = 8 warps each; warp w owns units [64r+8w, +8) x
//   4 gate types (fragment algebra identical to R8; pointwise register-local).
//   Per-step handshake (race-free):
//     - every thread stores its 2 bf16x2 h-values into BOTH CTAs' next
//       h-fragment buffer (local STS.64 + DSMEM st.shared::cluster.u64)
//     - arrives with RELEASE.CLUSTER on both CTAs' step-parity mbarrier
//       (TWO barriers ping-pong by step -> no cross-phase arrival mixing)
//     - waits its local barrier with ACQUIRE.CLUSTER
//   W fragments: k-steps 0-5 in regs (48 regs), 6-7 in smem.
// ---------------------------------------------------------------------------
__global__ __launch_bounds__(256, 1) __cluster_dims__(2, 1, 1)
void lstm_tc_cluster(const float* __restrict__ G,
                     const float* __restrict__ Whh,   // [2][512][128] fp32
                     const int*   __restrict__ lens,
                     float*       __restrict__ h1,    // may be null
                     float*       __restrict__ hT,    // may be null
                     int write_seq)
{
    __shared__ __align__(16) unsigned wfrag[4096];   // [w][ks-6][gt][lane] x uint2
    __shared__ __align__(16) unsigned hfrag[2048];   // 2 buf x [ks][lane][4]
    __shared__ __align__(8)  ull      mbar_store[2];

    const int tid  = threadIdx.x;
    const int lane = tid & 31;
    const int w    = tid >> 5;            // warp 0..7
    const int g    = lane >> 2;           // groupID (batch row)
    const int t    = lane & 3;            // threadID in group
    const int bid  = blockIdx.x;
    const int r    = bid & 1;             // cluster rank (unit half)
    const int clu  = bid >> 1;            // cluster id
    const int dir  = clu >> 4;
    const int bb   = (clu & 15) * 16;
    const int q0   = 64 * r + 8 * w + 2 * t;   // this lane's first unit

    const unsigned mbarA   = smem_u32(&mbar_store[0]);
    const unsigned mbarB   = smem_u32(&mbar_store[1]);
    const unsigned hbase_a = smem_u32(hfrag);
    const unsigned peer    = 1 - r;

    const float* Wd = Whh + (size_t)dir * G4 * HID;

    if (tid == 0) { mbar_init(mbarA, 512); mbar_init(mbarB, 512); }

    // ---- build W fragments (B-frag: b0 = W[row][16ks+2t,+1], b1 = +8) ----
    unsigned wreg[48];
#pragma unroll
    for (int ks = 0; ks < 8; ks++) {
#pragma unroll
        for (int gt = 0; gt < 4; gt++) {
            const float* row = Wd + (size_t)(gt * 128 + 64 * r + 8 * w + g) * HID
                             + 16 * ks + 2 * t;
            float2 lo = *(const float2*)row;
            float2 hi = *(const float2*)(row + 8);
            unsigned b0 = pack_bf16(lo.x, lo.y);
            unsigned b1 = pack_bf16(hi.x, hi.y);
            if (ks < 6) {
                wreg[(ks * 4 + gt) * 2]     = b0;
                wreg[(ks * 4 + gt) * 2 + 1] = b1;
            } else {
                const unsigned idx = (((w * 2 + (ks - 6)) * 4 + gt) * 32 + lane) * 2;
                wfrag[idx]     = b0;
                wfrag[idx + 1] = b1;
            }
        }
    }

    // zero h-fragment buffer 0 (full 128-unit copy per CTA)
    hfrag[tid] = 0u; hfrag[tid + 256] = 0u;
    hfrag[tid + 512] = 0u; hfrag[tid + 768] = 0u;

    const int len0 = lens[bb + g];        // batch m = g
    const int len1 = lens[bb + g + 8];    // batch m = g+8
    int Tmax = 0;
#pragma unroll
    for (int i = 0; i < 16; i++) Tmax = max(Tmax, lens[bb + i]);

    // advancing gate-input pointers
    const long long dstep = dir ? -(long long)G4 : (long long)G4;
    const float* p0 = G + (((size_t)(dir * BATCH + bb + g))     << 18)
                        + (size_t)(dir ? (len0 - 1) : 0) * G4;
    const float* p1 = G + (((size_t)(dir * BATCH + bb + g + 8)) << 18)
                        + (size_t)(dir ? (len1 - 1) : 0) * G4;

    float c00 = 0.f, c01 = 0.f, c10 = 0.f, c11 = 0.f;
    float h00 = 0.f, h01 = 0.f, h10 = 0.f, h11 = 0.f;

    // publish slot: unit q0 -> ks = q0>>4, reg pair ((q0>>3)&1)*2
    const int ksp  = q0 >> 4;
    const int regA = ((q0 >> 3) & 1) ? 2 : 0;

    CLUSTER_SYNC();   // mbarrier init + smem fills visible cluster-wide

    // prefetch gate inputs for step 0
    float2 gva[4], gvb[4];
#pragma unroll
    for (int gt = 0; gt < 4; gt++) {
        gva[gt] = *(const float2*)(p0 + gt * 128 + q0);
        gvb[gt] = *(const float2*)(p1 + gt * 128 + q0);
    }

    int cur = 0;
    for (int s = 0; s < Tmax; s++) {
        // advance & prefetch next step's gate inputs
        if (s + 1 < len0) p0 += dstep;
        if (s + 1 < len1) p1 += dstep;
        float2 gna[4], gnb[4];
#pragma unroll
        for (int gt = 0; gt < 4; gt++) {
            gna[gt] = *(const float2*)(p0 + gt * 128 + q0);
            gnb[gt] = *(const float2*)(p1 + gt * 128 + q0);
        }

        // ---- mma: D[16 batches x own 32 gate-rows] over K=128 ----
        float acc[4][4];
#pragma unroll
        for (int gt = 0; gt < 4; gt++)
#pragma unroll
            for (int c = 0; c < 4; c++) acc[gt][c] = 0.f;

        const unsigned hb = cur * 1024;
#pragma unroll
        for (int ks = 0; ks < 8; ks++) {
            uint4 av = *(const uint4*)&hfrag[hb + ks * 128 + lane * 4];
            unsigned a[4] = { av.x, av.y, av.z, av.w };
            if (ks < 6) {
#pragma unroll
                for (int gt = 0; gt < 4; gt++)
                    mma_bf16(acc[gt], a, wreg[(ks * 4 + gt) * 2],
                                         wreg[(ks * 4 + gt) * 2 + 1]);
            } else {
#pragma unroll
                for (int gt = 0; gt < 4; gt++) {
                    uint2 bfr = *(const uint2*)
                        &wfrag[(((w * 2 + (ks - 6)) * 4 + gt) * 32 + lane) * 2];
                    mma_bf16(acc[gt], a, bfr.x, bfr.y);
                }
            }
        }

        // ---- pointwise, batch g (acc cols 0,1) ----
        if (s < len0) {
            const float pi0 = acc[0][0] + gva[0].x, pi1 = acc[0][1] + gva[0].y;
            const float pf0 = acc[1][0] + gva[1].x, pf1 = acc[1][1] + gva[1].y;
            const float pg0 = acc[2][0] + gva[2].x, pg1 = acc[2][1] + gva[2].y;
            const float po0 = acc[3][0] + gva[3].x, po1 = acc[3][1] + gva[3].y;
            c00 = fmaf(sigm_fast(pf0), c00, sigm_fast(pi0) * tanh_fast(pg0));
            c01 = fmaf(sigm_fast(pf1), c01, sigm_fast(pi1) * tanh_fast(pg1));
            h00 = sigm_fast(po0) * tanh_fast(c00);
            h01 = sigm_fast(po1) * tanh_fast(c01);
            if (write_seq) {
                const int tt = dir ? (len0 - 1 - s) : s;
                *(float2*)&h1[((size_t)(bb + g) * TLEN + tt) * (2 * HID) + dir * HID + q0]
                    = make_float2(h00, h01);
            }
        }
        // ---- pointwise, batch g+8 (acc cols 2,3) ----
        if (s < len1) {
            const float pi0 = acc[0][2] + gvb[0].x, pi1 = acc[0][3] + gvb[0].y;
            const float pf0 = acc[1][2] + gvb[1].x, pf1 = acc[1][3] + gvb[1].y;
            const float pg0 = acc[2][2] + gvb[2].x, pg1 = acc[2][3] + gvb[2].y;
            const float po0 = acc[3][2] + gvb[3].x, po1 = acc[3][3] + gvb[3].y;
            c10 = fmaf(sigm_fast(pf0), c10, sigm_fast(pi0) * tanh_fast(pg0));
            c11 = fmaf(sigm_fast(pf1), c11, sigm_fast(pi1) * tanh_fast(pg1));
            h10 = sigm_fast(po0) * tanh_fast(c10);
            h11 = sigm_fast(po1) * tanh_fast(c11);
            if (write_seq) {
                const int tt = dir ? (len1 - 1 - s) : s;
                *(float2*)&h1[((size_t)(bb + g + 8) * TLEN + tt) * (2 * HID) + dir * HID + q0]
                    = make_float2(h10, h11);
            }
        }

        // ---- publish h into BOTH CTAs' next buffer (A-frag order) ----
        const unsigned vlo = pack_bf16(h00, h01);     // batch-g slot
        const unsigned vhi = pack_bf16(h10, h11);     // batch-(g+8) slot
        const unsigned ofs = (cur ^ 1) * 1024 + ksp * 128 + lane * 4 + regA;
        {   // local store (STS.64)
            ull v; asm("mov.b64 %0, {%1,%2};" : "=l"(v) : "r"(vlo), "r"(vhi));
            *(ull*)&hfrag[ofs] = v;
        }
        st_cluster_u64(hbase_a + ofs * 4, peer, vlo, vhi);   // DSMEM store

        // ping-pong barrier: step s uses barrier s&1, phase parity (s>>1)&1
        const unsigned mb = (s & 1) ? mbarB : mbarA;
        mbar_arrive_local(mb);
        mbar_arrive_remote(mb, peer);
        mbar_wait(mb, (s >> 1) & 1);
        cur ^= 1;

#pragma unroll
        for (int gt = 0; gt < 4; gt++) { gva[gt] = gna[gt]; gvb[gt] = gnb[gt]; }
    }

    if (hT) {
        *(float2*)&hT[((size_t)(dir * BATCH + bb + g))     * HID + q0] = make_float2(h00, h01);
        *(float2*)&hT[((size_t)(dir * BATCH + bb + g + 8)) * HID + q0] = make_float2(h10, h11);
    }

    if (write_seq) {
        // zero-fill padded region; CTA r covers its 64 units
        for (int qq = 0; qq < 16; qq++) {
            const int b  = bb + qq;
            const int lq = lens[b];
            const int ntail = (TLEN - lq) * 64;
            for (int idx = tid; idx < ntail; idx += 256) {
                const int tt = lq + (idx >> 6);
                const int k  = 64 * r + (idx & 63);
                h1[((size_t)b * TLEN + tt) * (2 * HID) + dir * HID + k] = 0.f;
            }
        }
    }

    CLUSTER_SYNC();   // no CTA exits while peer DSMEM traffic could be in flight
}

// ---------------------------------------------------------------------------
// FC + log_softmax.  h = concat([hT_backward, hT_forward]).
// ---------------------------------------------------------------------------
__global__ __launch_bounds__(32)
void fc_kernel(const float* __restrict__ HT,    // [2][256][128] (dir0=fwd, dir1=bwd)
               const float* __restrict__ Wfc,   // [12][256]
               const float* __restrict__ bfc,   // [12]
               float*       __restrict__ out)   // [256][12]
{
    const int b = blockIdx.x;
    const int c = threadIdx.x;
    float acc = 0.f;
    if (c < NCLS) {
        acc = bfc[c];
        const float* hb = HT + ((size_t)BATCH + b) * HID;  // backward (first half)
        const float* hf = HT + (size_t)b * HID;            // forward  (second half)
        const float* w  = Wfc + c * (2 * HID);
#pragma unroll 4
        for (int k = 0; k < HID; k++) acc = fmaf(w[k], hb[k], acc);
#pragma unroll 4
        for (int k = 0; k < HID; k++) acc = fmaf(w[HID + k], hf[k], acc);
    }
    float mx = (c < NCLS) ? acc : -3.4e38f;
#pragma unroll
    for (int o = 16; o; o >>= 1) mx = fmaxf(mx, __shfl_xor_sync(0xffffffffu, mx, o));
    float e = (c < NCLS) ? expf(acc - mx) : 0.f;
    float ssum = e;
#pragma unroll
    for (int o = 16; o; o >>= 1) ssum += __shfl_xor_sync(0xffffffffu, ssum, o);
    if (c < NCLS) out[b * NCLS + c] = acc - mx - logf(ssum);
}

// ---------------------------------------------------------------------------
// Launch
// ---------------------------------------------------------------------------
extern "C" void kernel_launch(void* const* d_in, const int* in_sizes, int n_in,
                              void* d_out, int out_size)
{
    const float* X    = (const float*)d_in[0];
    const int*   lens = (const int*)  d_in[1];
    const float* Wih0 = (const float*)d_in[2];
    const float* Whh0 = (const float*)d_in[3];
    const float* b0   = (const float*)d_in[4];
    const float* Wih1 = (const float*)d_in[5];
    const float* Whh1 = (const float*)d_in[6];
    const float* b1   = (const float*)d_in[7];
    const float* Wfc  = (const float*)d_in[8];
    const float* bfc  = (const float*)d_in[9];
    float* out = (float*)d_out;

    float *G0, *G1, *H1, *HT;
    cudaGetSymbolAddress((void**)&G0, g_G0);
    cudaGetSymbolAddress((void**)&G1, g_G1);
    cudaGetSymbolAddress((void**)&H1, g_H1);
    cudaGetSymbolAddress((void**)&HT, g_HT);

    dim3 gemm_grid(1024 / 128, MROWS / 128);   // 8 n-tiles x 1024 m-tiles

    // layer 0: input gates (tf32 TC), then clustered recurrence -> H1
    gate_gemm_tc<DIN><<<gemm_grid, 256>>>(X, Wih0, b0, lens, G0);
    lstm_tc_cluster<<<64, 256>>>(G0, Whh0, lens, H1, nullptr, 1);

    // layer 1: input gates over H1 (tf32 TC), clustered recurrence -> hT
    gate_gemm_tc<2 * HID><<<gemm_grid, 256>>>(H1, Wih1, b1, lens, G1);
    lstm_tc_cluster<<<64, 256>>>(G1, Whh1, lens, nullptr, HT, 0);

    // classifier head
    fc_kernel<<<BATCH, 32>>>(HT, Wfc, bfc, out);
}

// round 11
// speedup vs baseline: 1.2569x; 1.2569x over previous
#include <cuda_runtime.h>
#include <cuda_bf16.h>
#include <math.h>

// ---------------------------------------------------------------------------
// Problem constants
// ---------------------------------------------------------------------------
#define BATCH 256
#define TLEN  512
#define DIN   64
#define HID   128
#define G4    512              // 4*H
#define NCLS  12
#define MROWS (BATCH * TLEN)   // 131072

typedef unsigned long long ull;

// ---- helpers ----
// pack two f32 -> bf16x2 (low = first arg)
__device__ __forceinline__ unsigned pack_bf16(float lo, float hi) {
    unsigned r;
    asm("cvt.rn.bf16x2.f32 %0, %1, %2;" : "=r"(r) : "f"(hi), "f"(lo));
    return r;
}
__device__ __forceinline__ void mma_bf16(float d[4], const unsigned a[4],
                                         unsigned b0, unsigned b1) {
    asm("mma.sync.aligned.m16n8k16.row.col.f32.bf16.bf16.f32 "
        "{%0,%1,%2,%3},{%4,%5,%6,%7},{%8,%9},{%0,%1,%2,%3};"
        : "+f"(d[0]), "+f"(d[1]), "+f"(d[2]), "+f"(d[3])
        : "r"(a[0]), "r"(a[1]), "r"(a[2]), "r"(a[3]), "r"(b0), "r"(b1));
}
__device__ __forceinline__ float tanh_fast(float x) {
    float y; asm("tanh.approx.f32 %0, %1;" : "=f"(y) : "f"(x)); return y;
}
__device__ __forceinline__ float sigm_fast(float x) {
    return fmaf(0.5f, tanh_fast(0.5f * x), 0.5f);
}
__device__ __forceinline__ unsigned smem_u32(const void* p) {
    unsigned a;
    asm("{ .reg .u64 t; cvta.to.shared.u64 t, %1; cvt.u32.u64 %0, t; }"
        : "=r"(a) : "l"(p));
    return a;
}
__device__ __forceinline__ void ldsm_x4(unsigned r[4], unsigned addr) {
    asm volatile("ldmatrix.sync.aligned.m8n8.x4.shared.b16 {%0,%1,%2,%3}, [%4];"
                 : "=r"(r[0]), "=r"(r[1]), "=r"(r[2]), "=r"(r[3]) : "r"(addr));
}

// ---------------------------------------------------------------------------
// Scratch (device globals; allocation in kernel_launch is forbidden)
// ---------------------------------------------------------------------------
__device__ float g_G0[(size_t)2 * BATCH * TLEN * G4];   // layer0 gate pre-acts [dir][b][t][g]
__device__ float g_G1[(size_t)2 * BATCH * TLEN * G4];   // layer1 gate pre-acts
__device__ float g_H1[(size_t)BATCH * TLEN * 2 * HID];  // layer0 output [b][t][256]
__device__ float g_HT[(size_t)2 * BATCH * HID];         // layer1 final hidden [dir][b][128]

// ---------------------------------------------------------------------------
// Gate-input GEMM on tensor cores, bf16 mma.m16n8k16 + ldmatrix ("NT"):
//   G[dir][b][t][g] = A[m][:] . W[n][:] + bias[n]
//   CTA tile 128x128, BK=32, 8 warps (4m x 2n), warp tile 32x64.
//   Smem rows padded to 40 b16 (80 B) -> all 8 ldmatrix phases bank-distinct.
//   M-tiles entirely past len[b] are skipped (values never read downstream).
// ---------------------------------------------------------------------------
template <int KDIM>
__global__ __launch_bounds__(256, 2)
void gate_gemm_bf16(const float* __restrict__ A,
                    const float* __restrict__ W,
                    const float* __restrict__ bias,
                    const int*   __restrict__ lens,
                    float*       __restrict__ G)
{
    constexpr int BM = 128, BN = 128, BK = 32, LD = 40;   // LD in b16 elems
    __shared__ __align__(16) __nv_bfloat16 As[BM * LD];
    __shared__ __align__(16) __nv_bfloat16 Ws[BN * LD];

    const int m0 = blockIdx.y * BM;
    const int n0 = blockIdx.x * BN;
    const int b  = m0 >> 9;                 // 128 | 512 -> one batch per tile
    if ((m0 & 511) >= lens[b]) return;      // whole tile is padding

    const int tid  = threadIdx.x;
    const int lane = tid & 31;
    const int w    = tid >> 5;
    const int g    = lane >> 2;             // groupID
    const int t    = lane & 3;              // threadID in group
    const int wm   = w >> 1;                // m warp 0..3 (32 rows each)
    const int wn   = w & 1;                 // n warp 0..1 (64 cols each)

    // loader: thread covers 16 consecutive k of one row
    const int lrow = tid >> 1;
    const int lch  = (tid & 1) * 16;

    // ldmatrix lane -> matrix/row decomposition
    const int lq = lane >> 3;               // matrix index 0..3
    const int lr = lane & 7;                // row within matrix
    const unsigned sA = smem_u32(As);
    const unsigned sW = smem_u32(Ws);
    // byte offsets for this lane's ldmatrix row pointers (col part added per kk)
    const unsigned aoff0 = ((wm * 32 +      (lq & 1) * 8 + lr) * LD + (lq >> 1) * 8) * 2;
    const unsigned aoff1 = ((wm * 32 + 16 + (lq & 1) * 8 + lr) * LD + (lq >> 1) * 8) * 2;
    unsigned boff[4];
#pragma unroll
    for (int p = 0; p < 4; p++)
        boff[p] = ((wn * 64 + p * 16 + (lq & 1) * 8 + lr) * LD + (lq >> 1) * 8) * 2;

    float d[2][8][4];
#pragma unroll
    for (int mi = 0; mi < 2; mi++)
#pragma unroll
        for (int ni = 0; ni < 8; ni++)
#pragma unroll
            for (int c = 0; c < 4; c++) d[mi][ni][c] = 0.f;

    for (int k0 = 0; k0 < KDIM; k0 += BK) {
        // global load: 16 fp32 of A-row + 16 fp32 of W-row per thread
        float4 av[4], wv[4];
        const float* Ap = A + (size_t)(m0 + lrow) * KDIM + k0 + lch;
        const float* Wp = W + (size_t)(n0 + lrow) * KDIM + k0 + lch;
#pragma unroll
        for (int i = 0; i < 4; i++) {
            av[i] = *(const float4*)(Ap + 4 * i);
            wv[i] = *(const float4*)(Wp + 4 * i);
        }
        __syncthreads();
        {   // convert to bf16 and store as 2 uint4 each (row*80B is 16B-aligned)
            uint4 ua0 = { pack_bf16(av[0].x, av[0].y), pack_bf16(av[0].z, av[0].w),
                          pack_bf16(av[1].x, av[1].y), pack_bf16(av[1].z, av[1].w) };
            uint4 ua1 = { pack_bf16(av[2].x, av[2].y), pack_bf16(av[2].z, av[2].w),
                          pack_bf16(av[3].x, av[3].y), pack_bf16(av[3].z, av[3].w) };
            uint4 uw0 = { pack_bf16(wv[0].x, wv[0].y), pack_bf16(wv[0].z, wv[0].w),
                          pack_bf16(wv[1].x, wv[1].y), pack_bf16(wv[1].z, wv[1].w) };
            uint4 uw1 = { pack_bf16(wv[2].x, wv[2].y), pack_bf16(wv[2].z, wv[2].w),
                          pack_bf16(wv[3].x, wv[3].y), pack_bf16(wv[3].z, wv[3].w) };
            char* pa = (char*)As + lrow * (LD * 2) + lch * 2;
            char* pw = (char*)Ws + lrow * (LD * 2) + lch * 2;
            *(uint4*)pa = ua0; *(uint4*)(pa + 16) = ua1;
            *(uint4*)pw = uw0; *(uint4*)(pw + 16) = uw1;
        }
        __syncthreads();

#pragma unroll
        for (int kk = 0; kk < BK; kk += 16) {
            unsigned afr[2][4];
            ldsm_x4(afr[0], sA + aoff0 + kk * 2);
            ldsm_x4(afr[1], sA + aoff1 + kk * 2);
            unsigned bfr[8][2];
#pragma unroll
            for (int p = 0; p < 4; p++) {
                unsigned tmp[4];
                ldsm_x4(tmp, sW + boff[p] + kk * 2);
                bfr[2 * p][0]     = tmp[0];
                bfr[2 * p + 1][0] = tmp[1];
                bfr[2 * p][1]     = tmp[2];
                bfr[2 * p + 1][1] = tmp[3];
            }
#pragma unroll
            for (int ni = 0; ni < 8; ni++) {
                mma_bf16(d[0][ni], afr[0], bfr[ni][0], bfr[ni][1]);
                mma_bf16(d[1][ni], afr[1], bfr[ni][0], bfr[ni][1]);
            }
        }
    }

    // epilogue: +bias, scatter to G[dir][b][t][g] as float2 (cols 2t, 2t+1)
#pragma unroll
    for (int ni = 0; ni < 8; ni++) {
        const int col  = n0 + wn * 64 + ni * 8 + 2 * t;
        const int dirn = col >> 9;
        const int gg   = col & 511;
        const float2 bv = *(const float2*)(bias + col);
#pragma unroll
        for (int mi = 0; mi < 2; mi++) {
            const int m  = m0 + wm * 32 + mi * 16 + g;
            const int tt = m & 511;
            const size_t base = ((((size_t)dirn * BATCH + b) * TLEN) + tt) * G4 + gg;
            float2 v0 = { d[mi][ni][0] + bv.x, d[mi][ni][1] + bv.y };
            float2 v1 = { d[mi][ni][2] + bv.x, d[mi][ni][3] + bv.y };
            *(float2*)&G[base]                  = v0;   // row m
            *(float2*)&G[base + 8 * (size_t)G4] = v1;   // row m+8
        }
    }
}

// ---------------------------------------------------------------------------
// Tensor-core LSTM recurrence (exact R8 kernel — proven 602 us/launch).
//   One CTA = (dir, 16 batches) -> 32 CTAs, 512 threads = 16 warps.
//   Warp w owns units [8w,8w+8) x 4 gate types; pointwise register-local.
//   W fragments: k-steps 0-5 in regs (48 regs), 6-7 in smem (32 KB).
//   Gate inputs prefetched one step ahead via advancing clamped pointers.
//   h published bf16x2 in A-fragment order, double-buffered, 1 barrier/step.
// ---------------------------------------------------------------------------
#define LSTM_TC_SMEM ((8192 + 2048) * 4)     // wfrag 32 KB + hfrag 2x4 KB

__global__ __launch_bounds__(512, 1)
void lstm_tc_kernel(const float* __restrict__ G,
                    const float* __restrict__ Whh,   // [2][512][128] fp32
                    const int*   __restrict__ lens,
                    float*       __restrict__ h1,    // may be null
                    float*       __restrict__ hT,    // may be null
                    int write_seq)
{
    extern __shared__ unsigned usm[];
    unsigned* wfrag = usm;            // [w][ks-6][gt][lane] x uint2 : 8192 u32
    unsigned* hfrag = usm + 8192;     // 2 buffers x [ks][lane][4]   : 2048 u32

    const int tid  = threadIdx.x;
    const int lane = tid & 31;
    const int w    = tid >> 5;        // warp 0..15 -> units [8w, 8w+8)
    const int g    = lane >> 2;       // groupID
    const int t    = lane & 3;        // threadID in group
    const int q0   = 8 * w + 2 * t;   // this lane's first unit

    const int dir = blockIdx.x >> 4;
    const int bb  = (blockIdx.x & 15) * 16;

    const float* Wd = Whh + (size_t)dir * G4 * HID;

    // ---- build W fragments (B-frag layout: b0 = W[row][16ks+2t, +1]) ----
    unsigned wreg[48];
#pragma unroll
    for (int ks = 0; ks < 8; ks++) {
#pragma unroll
        for (int gt = 0; gt < 4; gt++) {
            const float* row = Wd + (size_t)(gt * 128 + 8 * w + g) * HID + 16 * ks + 2 * t;
            float2 lo = *(const float2*)row;
            float2 hi = *(const float2*)(row + 8);
            unsigned b0 = pack_bf16(lo.x, lo.y);
            unsigned b1 = pack_bf16(hi.x, hi.y);
            if (ks < 6) {
                wreg[(ks * 4 + gt) * 2]     = b0;
                wreg[(ks * 4 + gt) * 2 + 1] = b1;
            } else {
                const unsigned idx = (((w * 2 + (ks - 6)) * 4 + gt) * 32 + lane) * 2;
                wfrag[idx]     = b0;
                wfrag[idx + 1] = b1;
            }
        }
    }

    // zero h-fragment buffer 0
    hfrag[tid]       = 0u;
    hfrag[tid + 512] = 0u;

    const int len0 = lens[bb + g];        // batch m = g
    const int len1 = lens[bb + g + 8];    // batch m = g+8
    int Tmax = 0;
#pragma unroll
    for (int i = 0; i < 16; i++) Tmax = max(Tmax, lens[bb + i]);

    // advancing gate-input pointers (start at t for step 0)
    const long long dstep = dir ? -(long long)G4 : (long long)G4;
    const float* p0 = G + (((size_t)(dir * BATCH + bb + g))     << 18)
                        + (size_t)(dir ? (len0 - 1) : 0) * G4;
    const float* p1 = G + (((size_t)(dir * BATCH + bb + g + 8)) << 18)
                        + (size_t)(dir ? (len1 - 1) : 0) * G4;

    float c00 = 0.f, c01 = 0.f, c10 = 0.f, c11 = 0.f;   // cell state (2b x 2u)
    float h00 = 0.f, h01 = 0.f, h10 = 0.f, h11 = 0.f;

    // h-frag publish slot
    const int regA = (w & 1) ? 2 : 0;
    const int ksp  = w >> 1;

    __syncthreads();

    // prefetch gate inputs for step 0
    float2 gva[4], gvb[4];
#pragma unroll
    for (int gt = 0; gt < 4; gt++) {
        gva[gt] = *(const float2*)(p0 + gt * 128 + q0);
        gvb[gt] = *(const float2*)(p1 + gt * 128 + q0);
    }

    int cur = 0;
    for (int s = 0; s < Tmax; s++) {
        // ---- advance pointers & prefetch step s+1 (hidden behind mma) ----
        if (s + 1 < len0) p0 += dstep;
        if (s + 1 < len1) p1 += dstep;
        float2 gna[4], gnb[4];
#pragma unroll
        for (int gt = 0; gt < 4; gt++) {
            gna[gt] = *(const float2*)(p0 + gt * 128 + q0);
            gnb[gt] = *(const float2*)(p1 + gt * 128 + q0);
        }

        // ---- mma: D[16 x own 32 gate-rows] over K=128 ----
        float acc[4][4];
#pragma unroll
        for (int gt = 0; gt < 4; gt++)
#pragma unroll
            for (int c = 0; c < 4; c++) acc[gt][c] = 0.f;

        const unsigned hbase = cur * 1024;
#pragma unroll
        for (int ks = 0; ks < 8; ks++) {
            uint4 av = *(const uint4*)&hfrag[hbase + ks * 128 + lane * 4];
            unsigned a[4] = { av.x, av.y, av.z, av.w };
            if (ks < 6) {
#pragma unroll
                for (int gt = 0; gt < 4; gt++)
                    mma_bf16(acc[gt], a, wreg[(ks * 4 + gt) * 2],
                                         wreg[(ks * 4 + gt) * 2 + 1]);
            } else {
#pragma unroll
                for (int gt = 0; gt < 4; gt++) {
                    uint2 bfr = *(const uint2*)
                        &wfrag[(((w * 2 + (ks - 6)) * 4 + gt) * 32 + lane) * 2];
                    mma_bf16(acc[gt], a, bfr.x, bfr.y);
                }
            }
        }

        // ---- pointwise, batch m=g (acc cols 0,1) ----
        if (s < len0) {
            const float pi0 = acc[0][0] + gva[0].x, pi1 = acc[0][1] + gva[0].y;
            const float pf0 = acc[1][0] + gva[1].x, pf1 = acc[1][1] + gva[1].y;
            const float pg0 = acc[2][0] + gva[2].x, pg1 = acc[2][1] + gva[2].y;
            const float po0 = acc[3][0] + gva[3].x, po1 = acc[3][1] + gva[3].y;
            c00 = fmaf(sigm_fast(pf0), c00, sigm_fast(pi0) * tanh_fast(pg0));
            c01 = fmaf(sigm_fast(pf1), c01, sigm_fast(pi1) * tanh_fast(pg1));
            h00 = sigm_fast(po0) * tanh_fast(c00);
            h01 = sigm_fast(po1) * tanh_fast(c01);
            if (write_seq) {
                const int tt = dir ? (len0 - 1 - s) : s;
                *(float2*)&h1[((size_t)(bb + g) * TLEN + tt) * (2 * HID) + dir * HID + q0]
                    = make_float2(h00, h01);
            }
        }
        // ---- pointwise, batch m=g+8 (acc cols 2,3) ----
        if (s < len1) {
            const float pi0 = acc[0][2] + gvb[0].x, pi1 = acc[0][3] + gvb[0].y;
            const float pf0 = acc[1][2] + gvb[1].x, pf1 = acc[1][3] + gvb[1].y;
            const float pg0 = acc[2][2] + gvb[2].x, pg1 = acc[2][3] + gvb[2].y;
            const float po0 = acc[3][2] + gvb[3].x, po1 = acc[3][3] + gvb[3].y;
            c10 = fmaf(sigm_fast(pf0), c10, sigm_fast(pi0) * tanh_fast(pg0));
            c11 = fmaf(sigm_fast(pf1), c11, sigm_fast(pi1) * tanh_fast(pg1));
            h10 = sigm_fast(po0) * tanh_fast(c10);
            h11 = sigm_fast(po1) * tanh_fast(c11);
            if (write_seq) {
                const int tt = dir ? (len1 - 1 - s) : s;
                *(float2*)&h1[((size_t)(bb + g + 8) * TLEN + tt) * (2 * HID) + dir * HID + q0]
                    = make_float2(h10, h11);
            }
        }

        // ---- publish h (bf16x2) into the other buffer, A-frag order ----
        const unsigned obase = (cur ^ 1) * 1024 + ksp * 128 + lane * 4;
        hfrag[obase + regA]     = pack_bf16(h00, h01);
        hfrag[obase + regA + 1] = pack_bf16(h10, h11);
        __syncthreads();
        cur ^= 1;

#pragma unroll
        for (int gt = 0; gt < 4; gt++) { gva[gt] = gna[gt]; gvb[gt] = gnb[gt]; }
    }

    if (hT) {
        *(float2*)&hT[((size_t)(dir * BATCH + bb + g))     * HID + q0] = make_float2(h00, h01);
        *(float2*)&hT[((size_t)(dir * BATCH + bb + g + 8)) * HID + q0] = make_float2(h10, h11);
    }

    if (write_seq) {
        // zero-fill padded region (reference masks hs to zero at t >= len)
        for (int qq = 0; qq < 16; qq++) {
            const int b  = bb + qq;
            const int lq = lens[b];
            const int ntail = (TLEN - lq) * HID;
            for (int idx = tid; idx < ntail; idx += 512) {
                const int tt = lq + (idx >> 7);
                const int k  = idx & 127;
                h1[((size_t)b * TLEN + tt) * (2 * HID) + dir * HID + k] = 0.f;
            }
        }
    }
}

// ---------------------------------------------------------------------------
// FC + log_softmax.  h = concat([hT_backward, hT_forward]).
// ---------------------------------------------------------------------------
__global__ __launch_bounds__(32)
void fc_kernel(const float* __restrict__ HT,    // [2][256][128] (dir0=fwd, dir1=bwd)
               const float* __restrict__ Wfc,   // [12][256]
               const float* __restrict__ bfc,   // [12]
               float*       __restrict__ out)   // [256][12]
{
    const int b = blockIdx.x;
    const int c = threadIdx.x;
    float acc = 0.f;
    if (c < NCLS) {
        acc = bfc[c];
        const float* hb = HT + ((size_t)BATCH + b) * HID;  // backward (first half)
        const float* hf = HT + (size_t)b * HID;            // forward  (second half)
        const float* w  = Wfc + c * (2 * HID);
#pragma unroll 4
        for (int k = 0; k < HID; k++) acc = fmaf(w[k], hb[k], acc);
#pragma unroll 4
        for (int k = 0; k < HID; k++) acc = fmaf(w[HID + k], hf[k], acc);
    }
    float mx = (c < NCLS) ? acc : -3.4e38f;
#pragma unroll
    for (int o = 16; o; o >>= 1) mx = fmaxf(mx, __shfl_xor_sync(0xffffffffu, mx, o));
    float e = (c < NCLS) ? expf(acc - mx) : 0.f;
    float ssum = e;
#pragma unroll
    for (int o = 16; o; o >>= 1) ssum += __shfl_xor_sync(0xffffffffu, ssum, o);
    if (c < NCLS) out[b * NCLS + c] = acc - mx - logf(ssum);
}

// ---------------------------------------------------------------------------
// Launch
// ---------------------------------------------------------------------------
extern "C" void kernel_launch(void* const* d_in, const int* in_sizes, int n_in,
                              void* d_out, int out_size)
{
    const float* X    = (const float*)d_in[0];
    const int*   lens = (const int*)  d_in[1];
    const float* Wih0 = (const float*)d_in[2];
    const float* Whh0 = (const float*)d_in[3];
    const float* b0   = (const float*)d_in[4];
    const float* Wih1 = (const float*)d_in[5];
    const float* Whh1 = (const float*)d_in[6];
    const float* b1   = (const float*)d_in[7];
    const float* Wfc  = (const float*)d_in[8];
    const float* bfc  = (const float*)d_in[9];
    float* out = (float*)d_out;

    float *G0, *G1, *H1, *HT;
    cudaGetSymbolAddress((void**)&G0, g_G0);
    cudaGetSymbolAddress((void**)&G1, g_G1);
    cudaGetSymbolAddress((void**)&H1, g_H1);
    cudaGetSymbolAddress((void**)&HT, g_HT);

    cudaFuncSetAttribute(lstm_tc_kernel, cudaFuncAttributeMaxDynamicSharedMemorySize,
                         LSTM_TC_SMEM);

    dim3 gemm_grid(1024 / 128, MROWS / 128);   // 8 n-tiles x 1024 m-tiles

    // layer 0: input gates (bf16 TC + ldmatrix), then recurrence -> H1
    gate_gemm_bf16<DIN><<<gemm_grid, 256>>>(X, Wih0, b0, lens, G0);
    lstm_tc_kernel<<<32, 512, LSTM_TC_SMEM>>>(G0, Whh0, lens, H1, nullptr, 1);

    // layer 1: input gates over H1 (bf16 TC), recurrence -> final hiddens
    gate_gemm_bf16<2 * HID><<<gemm_grid, 256>>>(H1, Wih1, b1, lens, G1);
    lstm_tc_kernel<<<32, 512, LSTM_TC_SMEM>>>(G1, Whh1, lens, nullptr, HT, 0);

    // classifier head
    fc_kernel<<<BATCH, 32>>>(HT, Wfc, bfc, out);
}

// round 12
// speedup vs baseline: 1.5446x; 1.2288x over previous
#include <cuda_runtime.h>
#include <cuda_bf16.h>
#include <math.h>

// ---------------------------------------------------------------------------
// Problem constants
// ---------------------------------------------------------------------------
#define BATCH 256
#define TLEN  512
#define DIN   64
#define HID   128
#define G4    512              // 4*H
#define NCLS  12
#define MROWS (BATCH * TLEN)   // 131072

typedef unsigned long long ull;

// ---- helpers ----
// pack two f32 -> bf16x2 (low = first arg)
__device__ __forceinline__ unsigned pack_bf16(float lo, float hi) {
    unsigned r;
    asm("cvt.rn.bf16x2.f32 %0, %1, %2;" : "=r"(r) : "f"(hi), "f"(lo));
    return r;
}
__device__ __forceinline__ void mma_bf16(float d[4], const unsigned a[4],
                                         unsigned b0, unsigned b1) {
    asm("mma.sync.aligned.m16n8k16.row.col.f32.bf16.bf16.f32 "
        "{%0,%1,%2,%3},{%4,%5,%6,%7},{%8,%9},{%0,%1,%2,%3};"
        : "+f"(d[0]), "+f"(d[1]), "+f"(d[2]), "+f"(d[3])
        : "r"(a[0]), "r"(a[1]), "r"(a[2]), "r"(a[3]), "r"(b0), "r"(b1));
}
__device__ __forceinline__ float tanh_fast(float x) {
    float y; asm("tanh.approx.f32 %0, %1;" : "=f"(y) : "f"(x)); return y;
}
__device__ __forceinline__ float sigm_fast(float x) {
    return fmaf(0.5f, tanh_fast(0.5f * x), 0.5f);
}
__device__ __forceinline__ unsigned smem_u32(const void* p) {
    unsigned a;
    asm("{ .reg .u64 t; cvta.to.shared.u64 t, %1; cvt.u32.u64 %0, t; }"
        : "=r"(a) : "l"(p));
    return a;
}
__device__ __forceinline__ void ldsm_x4(unsigned r[4], unsigned addr) {
    asm volatile("ldmatrix.sync.aligned.m8n8.x4.shared.b16 {%0,%1,%2,%3}, [%4];"
                 : "=r"(r[0]), "=r"(r[1]), "=r"(r[2]), "=r"(r[3]) : "r"(addr));
}

// ---------------------------------------------------------------------------
// Scratch (device globals; allocation in kernel_launch is forbidden)
// ---------------------------------------------------------------------------
__device__ float g_G0[(size_t)2 * BATCH * TLEN * G4];   // layer0 gate pre-acts [dir][b][t][g]
__device__ float g_G1[(size_t)2 * BATCH * TLEN * G4];   // layer1 gate pre-acts
__device__ float g_H1[(size_t)BATCH * TLEN * 2 * HID];  // layer0 output [b][t][256]
__device__ float g_HT[(size_t)2 * BATCH * HID];         // layer1 final hidden [dir][b][128]

// ---------------------------------------------------------------------------
// Gate-input GEMM on tensor cores, bf16 mma.m16n8k16 + ldmatrix ("NT").
//   Unchanged from R11 (proven): CTA tile 128x128, BK=32, 8 warps.
// ---------------------------------------------------------------------------
template <int KDIM>
__global__ __launch_bounds__(256, 2)
void gate_gemm_bf16(const float* __restrict__ A,
                    const float* __restrict__ W,
                    const float* __restrict__ bias,
                    const int*   __restrict__ lens,
                    float*       __restrict__ G)
{
    constexpr int BM = 128, BN = 128, BK = 32, LD = 40;   // LD in b16 elems
    __shared__ __align__(16) __nv_bfloat16 As[BM * LD];
    __shared__ __align__(16) __nv_bfloat16 Ws[BN * LD];

    const int m0 = blockIdx.y * BM;
    const int n0 = blockIdx.x * BN;
    const int b  = m0 >> 9;                 // 128 | 512 -> one batch per tile
    if ((m0 & 511) >= lens[b]) return;      // whole tile is padding

    const int tid  = threadIdx.x;
    const int lane = tid & 31;
    const int w    = tid >> 5;
    const int g    = lane >> 2;             // groupID
    const int t    = lane & 3;              // threadID in group
    const int wm   = w >> 1;                // m warp 0..3 (32 rows each)
    const int wn   = w & 1;                 // n warp 0..1 (64 cols each)

    const int lrow = tid >> 1;
    const int lch  = (tid & 1) * 16;

    const int lq = lane >> 3;               // matrix index 0..3
    const int lr = lane & 7;                // row within matrix
    const unsigned sA = smem_u32(As);
    const unsigned sW = smem_u32(Ws);
    const unsigned aoff0 = ((wm * 32 +      (lq & 1) * 8 + lr) * LD + (lq >> 1) * 8) * 2;
    const unsigned aoff1 = ((wm * 32 + 16 + (lq & 1) * 8 + lr) * LD + (lq >> 1) * 8) * 2;
    unsigned boff[4];
#pragma unroll
    for (int p = 0; p < 4; p++)
        boff[p] = ((wn * 64 + p * 16 + (lq & 1) * 8 + lr) * LD + (lq >> 1) * 8) * 2;

    float d[2][8][4];
#pragma unroll
    for (int mi = 0; mi < 2; mi++)
#pragma unroll
        for (int ni = 0; ni < 8; ni++)
#pragma unroll
            for (int c = 0; c < 4; c++) d[mi][ni][c] = 0.f;

    for (int k0 = 0; k0 < KDIM; k0 += BK) {
        float4 av[4], wv[4];
        const float* Ap = A + (size_t)(m0 + lrow) * KDIM + k0 + lch;
        const float* Wp = W + (size_t)(n0 + lrow) * KDIM + k0 + lch;
#pragma unroll
        for (int i = 0; i < 4; i++) {
            av[i] = *(const float4*)(Ap + 4 * i);
            wv[i] = *(const float4*)(Wp + 4 * i);
        }
        __syncthreads();
        {
            uint4 ua0 = { pack_bf16(av[0].x, av[0].y), pack_bf16(av[0].z, av[0].w),
                          pack_bf16(av[1].x, av[1].y), pack_bf16(av[1].z, av[1].w) };
            uint4 ua1 = { pack_bf16(av[2].x, av[2].y), pack_bf16(av[2].z, av[2].w),
                          pack_bf16(av[3].x, av[3].y), pack_bf16(av[3].z, av[3].w) };
            uint4 uw0 = { pack_bf16(wv[0].x, wv[0].y), pack_bf16(wv[0].z, wv[0].w),
                          pack_bf16(wv[1].x, wv[1].y), pack_bf16(wv[1].z, wv[1].w) };
            uint4 uw1 = { pack_bf16(wv[2].x, wv[2].y), pack_bf16(wv[2].z, wv[2].w),
                          pack_bf16(wv[3].x, wv[3].y), pack_bf16(wv[3].z, wv[3].w) };
            char* pa = (char*)As + lrow * (LD * 2) + lch * 2;
            char* pw = (char*)Ws + lrow * (LD * 2) + lch * 2;
            *(uint4*)pa = ua0; *(uint4*)(pa + 16) = ua1;
            *(uint4*)pw = uw0; *(uint4*)(pw + 16) = uw1;
        }
        __syncthreads();

#pragma unroll
        for (int kk = 0; kk < BK; kk += 16) {
            unsigned afr[2][4];
            ldsm_x4(afr[0], sA + aoff0 + kk * 2);
            ldsm_x4(afr[1], sA + aoff1 + kk * 2);
            unsigned bfr[8][2];
#pragma unroll
            for (int p = 0; p < 4; p++) {
                unsigned tmp[4];
                ldsm_x4(tmp, sW + boff[p] + kk * 2);
                bfr[2 * p][0]     = tmp[0];
                bfr[2 * p + 1][0] = tmp[1];
                bfr[2 * p][1]     = tmp[2];
                bfr[2 * p + 1][1] = tmp[3];
            }
#pragma unroll
            for (int ni = 0; ni < 8; ni++) {
                mma_bf16(d[0][ni], afr[0], bfr[ni][0], bfr[ni][1]);
                mma_bf16(d[1][ni], afr[1], bfr[ni][0], bfr[ni][1]);
            }
        }
    }

#pragma unroll
    for (int ni = 0; ni < 8; ni++) {
        const int col  = n0 + wn * 64 + ni * 8 + 2 * t;
        const int dirn = col >> 9;
        const int gg   = col & 511;
        const float2 bv = *(const float2*)(bias + col);
#pragma unroll
        for (int mi = 0; mi < 2; mi++) {
            const int m  = m0 + wm * 32 + mi * 16 + g;
            const int tt = m & 511;
            const size_t base = ((((size_t)dirn * BATCH + b) * TLEN) + tt) * G4 + gg;
            float2 v0 = { d[mi][ni][0] + bv.x, d[mi][ni][1] + bv.y };
            float2 v1 = { d[mi][ni][2] + bv.x, d[mi][ni][3] + bv.y };
            *(float2*)&G[base]                  = v0;   // row m
            *(float2*)&G[base + 8 * (size_t)G4] = v1;   // row m+8
        }
    }
}

// ---------------------------------------------------------------------------
// Tensor-core LSTM recurrence, batch-split for 2x SM coverage.
//   One CTA = (dir, 8 batches) -> 64 CTAs (communication-free split: each
//   CTA's mma needs only ITS OWN batches' h rows).  512 threads = 16 warps;
//   warp w owns units [8w,8w+8) x 4 gate types — fragment algebra identical
//   to the proven R8/R11 kernel.  A-fragment rows 8-15 (batches 8-15, which
//   don't exist here) are zeroed once and never written; their accumulator
//   columns are ignored.  W: k-steps 0-5 in regs, 6-7 in smem; gv prefetch.
// ---------------------------------------------------------------------------
#define LSTM_TC_SMEM ((8192 + 2048) * 4)     // wfrag 32 KB + hfrag 2x4 KB

__global__ __launch_bounds__(512, 1)
void lstm_tc_kernel(const float* __restrict__ G,
                    const float* __restrict__ Whh,   // [2][512][128] fp32
                    const int*   __restrict__ lens,
                    float*       __restrict__ h1,    // may be null
                    float*       __restrict__ hT,    // may be null
                    int write_seq)
{
    extern __shared__ unsigned usm[];
    unsigned* wfrag = usm;            // [w][ks-6][gt][lane] x uint2 : 8192 u32
    unsigned* hfrag = usm + 8192;     // 2 buffers x [ks][lane][4]   : 2048 u32

    const int tid  = threadIdx.x;
    const int lane = tid & 31;
    const int w    = tid >> 5;        // warp 0..15 -> units [8w, 8w+8)
    const int g    = lane >> 2;       // groupID == batch row (0..7 valid)
    const int t    = lane & 3;        // threadID in group
    const int q0   = 8 * w + 2 * t;   // this lane's first unit

    const int dir = blockIdx.x >> 5;
    const int bb  = (blockIdx.x & 31) * 8;

    const float* Wd = Whh + (size_t)dir * G4 * HID;

    // ---- build W fragments (B-frag layout: b0 = W[row][16ks+2t, +1]) ----
    unsigned wreg[48];
#pragma unroll
    for (int ks = 0; ks < 8; ks++) {
#pragma unroll
        for (int gt = 0; gt < 4; gt++) {
            const float* row = Wd + (size_t)(gt * 128 + 8 * w + g) * HID + 16 * ks + 2 * t;
            float2 lo = *(const float2*)row;
            float2 hi = *(const float2*)(row + 8);
            unsigned b0 = pack_bf16(lo.x, lo.y);
            unsigned b1 = pack_bf16(hi.x, hi.y);
            if (ks < 6) {
                wreg[(ks * 4 + gt) * 2]     = b0;
                wreg[(ks * 4 + gt) * 2 + 1] = b1;
            } else {
                const unsigned idx = (((w * 2 + (ks - 6)) * 4 + gt) * 32 + lane) * 2;
                wfrag[idx]     = b0;
                wfrag[idx + 1] = b1;
            }
        }
    }

    // zero BOTH h-fragment buffers entirely: rows 8-15 (batches that don't
    // exist in this CTA) must stay zero forever.
    hfrag[tid]        = 0u;
    hfrag[tid + 512]  = 0u;
    hfrag[tid + 1024] = 0u;
    hfrag[tid + 1536] = 0u;

    const int len0 = lens[bb + g];        // this lane's batch
    int Tmax = 0;
#pragma unroll
    for (int i = 0; i < 8; i++) Tmax = max(Tmax, lens[bb + i]);

    // advancing gate-input pointer (starts at t for step 0)
    const long long dstep = dir ? -(long long)G4 : (long long)G4;
    const float* p0 = G + (((size_t)(dir * BATCH + bb + g)) << 18)
                        + (size_t)(dir ? (len0 - 1) : 0) * G4;

    float c00 = 0.f, c01 = 0.f;           // cell state (1 batch x 2 units)
    float h00 = 0.f, h01 = 0.f;

    // h-frag publish slot (row g only; row g+8 slot stays zero)
    const int regA = (w & 1) ? 2 : 0;
    const int ksp  = w >> 1;

    __syncthreads();

    // prefetch gate inputs for step 0
    float2 gva[4];
#pragma unroll
    for (int gt = 0; gt < 4; gt++)
        gva[gt] = *(const float2*)(p0 + gt * 128 + q0);

    int cur = 0;
    for (int s = 0; s < Tmax; s++) {
        // ---- advance pointer & prefetch step s+1 (hidden behind mma) ----
        if (s + 1 < len0) p0 += dstep;
        float2 gna[4];
#pragma unroll
        for (int gt = 0; gt < 4; gt++)
            gna[gt] = *(const float2*)(p0 + gt * 128 + q0);

        // ---- mma: D[8 batches x own 32 gate-rows] over K=128 ----
        float acc[4][4];
#pragma unroll
        for (int gt = 0; gt < 4; gt++)
#pragma unroll
            for (int c = 0; c < 4; c++) acc[gt][c] = 0.f;

        const unsigned hbase = cur * 1024;
#pragma unroll
        for (int ks = 0; ks < 8; ks++) {
            uint4 av = *(const uint4*)&hfrag[hbase + ks * 128 + lane * 4];
            unsigned a[4] = { av.x, av.y, av.z, av.w };
            if (ks < 6) {
#pragma unroll
                for (int gt = 0; gt < 4; gt++)
                    mma_bf16(acc[gt], a, wreg[(ks * 4 + gt) * 2],
                                         wreg[(ks * 4 + gt) * 2 + 1]);
            } else {
#pragma unroll
                for (int gt = 0; gt < 4; gt++) {
                    uint2 bfr = *(const uint2*)
                        &wfrag[(((w * 2 + (ks - 6)) * 4 + gt) * 32 + lane) * 2];
                    mma_bf16(acc[gt], a, bfr.x, bfr.y);
                }
            }
        }

        // ---- pointwise for batch bb+g (acc cols 0,1) ----
        if (s < len0) {
            const float pi0 = acc[0][0] + gva[0].x, pi1 = acc[0][1] + gva[0].y;
            const float pf0 = acc[1][0] + gva[1].x, pf1 = acc[1][1] + gva[1].y;
            const float pg0 = acc[2][0] + gva[2].x, pg1 = acc[2][1] + gva[2].y;
            const float po0 = acc[3][0] + gva[3].x, po1 = acc[3][1] + gva[3].y;
            c00 = fmaf(sigm_fast(pf0), c00, sigm_fast(pi0) * tanh_fast(pg0));
            c01 = fmaf(sigm_fast(pf1), c01, sigm_fast(pi1) * tanh_fast(pg1));
            h00 = sigm_fast(po0) * tanh_fast(c00);
            h01 = sigm_fast(po1) * tanh_fast(c01);
            if (write_seq) {
                const int tt = dir ? (len0 - 1 - s) : s;
                *(float2*)&h1[((size_t)(bb + g) * TLEN + tt) * (2 * HID) + dir * HID + q0]
                    = make_float2(h00, h01);
            }
        }

        // ---- publish h (bf16x2) into the other buffer, A-frag row g ----
        hfrag[(cur ^ 1) * 1024 + ksp * 128 + lane * 4 + regA] = pack_bf16(h00, h01);
        __syncthreads();
        cur ^= 1;

#pragma unroll
        for (int gt = 0; gt < 4; gt++) gva[gt] = gna[gt];
    }

    if (hT)
        *(float2*)&hT[((size_t)(dir * BATCH + bb + g)) * HID + q0] = make_float2(h00, h01);

    if (write_seq) {
        // zero-fill padded region (reference masks hs to zero at t >= len)
        for (int qq = 0; qq < 8; qq++) {
            const int b  = bb + qq;
            const int lq = lens[b];
            const int ntail = (TLEN - lq) * HID;
            for (int idx = tid; idx < ntail; idx += 512) {
                const int tt = lq + (idx >> 7);
                const int k  = idx & 127;
                h1[((size_t)b * TLEN + tt) * (2 * HID) + dir * HID + k] = 0.f;
            }
        }
    }
}

// ---------------------------------------------------------------------------
// FC + log_softmax.  h = concat([hT_backward, hT_forward]).
// ---------------------------------------------------------------------------
__global__ __launch_bounds__(32)
void fc_kernel(const float* __restrict__ HT,    // [2][256][128] (dir0=fwd, dir1=bwd)
               const float* __restrict__ Wfc,   // [12][256]
               const float* __restrict__ bfc,   // [12]
               float*       __restrict__ out)   // [256][12]
{
    const int b = blockIdx.x;
    const int c = threadIdx.x;
    float acc = 0.f;
    if (c < NCLS) {
        acc = bfc[c];
        const float* hb = HT + ((size_t)BATCH + b) * HID;  // backward (first half)
        const float* hf = HT + (size_t)b * HID;            // forward  (second half)
        const float* w  = Wfc + c * (2 * HID);
#pragma unroll 4
        for (int k = 0; k < HID; k++) acc = fmaf(w[k], hb[k], acc);
#pragma unroll 4
        for (int k = 0; k < HID; k++) acc = fmaf(w[HID + k], hf[k], acc);
    }
    float mx = (c < NCLS) ? acc : -3.4e38f;
#pragma unroll
    for (int o = 16; o; o >>= 1) mx = fmaxf(mx, __shfl_xor_sync(0xffffffffu, mx, o));
    float e = (c < NCLS) ? expf(acc - mx) : 0.f;
    float ssum = e;
#pragma unroll
    for (int o = 16; o; o >>= 1) ssum += __shfl_xor_sync(0xffffffffu, ssum, o);
    if (c < NCLS) out[b * NCLS + c] = acc - mx - logf(ssum);
}

// ---------------------------------------------------------------------------
// Launch
// ---------------------------------------------------------------------------
extern "C" void kernel_launch(void* const* d_in, const int* in_sizes, int n_in,
                              void* d_out, int out_size)
{
    const float* X    = (const float*)d_in[0];
    const int*   lens = (const int*)  d_in[1];
    const float* Wih0 = (const float*)d_in[2];
    const float* Whh0 = (const float*)d_in[3];
    const float* b0   = (const float*)d_in[4];
    const float* Wih1 = (const float*)d_in[5];
    const float* Whh1 = (const float*)d_in[6];
    const float* b1   = (const float*)d_in[7];
    const float* Wfc  = (const float*)d_in[8];
    const float* bfc  = (const float*)d_in[9];
    float* out = (float*)d_out;

    float *G0, *G1, *H1, *HT;
    cudaGetSymbolAddress((void**)&G0, g_G0);
    cudaGetSymbolAddress((void**)&G1, g_G1);
    cudaGetSymbolAddress((void**)&H1, g_H1);
    cudaGetSymbolAddress((void**)&HT, g_HT);

    cudaFuncSetAttribute(lstm_tc_kernel, cudaFuncAttributeMaxDynamicSharedMemorySize,
                         LSTM_TC_SMEM);

    dim3 gemm_grid(1024 / 128, MROWS / 128);   // 8 n-tiles x 1024 m-tiles

    // layer 0: input gates (bf16 TC + ldmatrix), then recurrence -> H1
    gate_gemm_bf16<DIN><<<gemm_grid, 256>>>(X, Wih0, b0, lens, G0);
    lstm_tc_kernel<<<64, 512, LSTM_TC_SMEM>>>(G0, Whh0, lens, H1, nullptr, 1);

    // layer 1: input gates over H1 (bf16 TC), recurrence -> final hiddens
    gate_gemm_bf16<2 * HID><<<gemm_grid, 256>>>(H1, Wih1, b1, lens, G1);
    lstm_tc_kernel<<<64, 512, LSTM_TC_SMEM>>>(G1, Whh1, lens, nullptr, HT, 0);

    // classifier head
    fc_kernel<<<BATCH, 32>>>(HT, Wfc, bfc, out);
}

// round 13
// speedup vs baseline: 1.7014x; 1.1015x over previous
#include <cuda_runtime.h>
#include <cuda_bf16.h>
#include <math.h>

// ---------------------------------------------------------------------------
// Problem constants
// ---------------------------------------------------------------------------
#define BATCH 256
#define TLEN  512
#define DIN   64
#define HID   128
#define G4    512              // 4*H
#define NCLS  12
#define MROWS (BATCH * TLEN)   // 131072

// ---- helpers ----
// pack two f32 -> bf16x2 (low = first arg)
__device__ __forceinline__ unsigned pack_bf16(float lo, float hi) {
    unsigned r;
    asm("cvt.rn.bf16x2.f32 %0, %1, %2;" : "=r"(r) : "f"(hi), "f"(lo));
    return r;
}
__device__ __forceinline__ void mma_bf16(float d[4], const unsigned a[4],
                                         unsigned b0, unsigned b1) {
    asm("mma.sync.aligned.m16n8k16.row.col.f32.bf16.bf16.f32 "
        "{%0,%1,%2,%3},{%4,%5,%6,%7},{%8,%9},{%0,%1,%2,%3};"
        : "+f"(d[0]), "+f"(d[1]), "+f"(d[2]), "+f"(d[3])
        : "r"(a[0]), "r"(a[1]), "r"(a[2]), "r"(a[3]), "r"(b0), "r"(b1));
}
__device__ __forceinline__ float tanh_fast(float x) {
    float y; asm("tanh.approx.f32 %0, %1;" : "=f"(y) : "f"(x)); return y;
}
__device__ __forceinline__ float sigm_fast(float x) {
    return fmaf(0.5f, tanh_fast(0.5f * x), 0.5f);
}
__device__ __forceinline__ unsigned smem_u32(const void* p) {
    unsigned a;
    asm("{ .reg .u64 t; cvta.to.shared.u64 t, %1; cvt.u32.u64 %0, t; }"
        : "=r"(a) : "l"(p));
    return a;
}
__device__ __forceinline__ void ldsm_x4(unsigned r[4], unsigned addr) {
    asm volatile("ldmatrix.sync.aligned.m8n8.x4.shared.b16 {%0,%1,%2,%3}, [%4];"
                 : "=r"(r[0]), "=r"(r[1]), "=r"(r[2]), "=r"(r[3]) : "r"(addr));
}
#define CP_ASYNC16(sm, gp) \
    asm volatile("cp.async.cg.shared.global [%0], [%1], 16;" :: "r"(sm), "l"(gp))
#define CP_COMMIT() asm volatile("cp.async.commit_group;")

// ---------------------------------------------------------------------------
// Scratch (device globals; allocation in kernel_launch is forbidden)
// ---------------------------------------------------------------------------
__device__ float g_G0[(size_t)2 * BATCH * TLEN * G4];   // layer0 gate pre-acts
__device__ float g_G1[(size_t)2 * BATCH * TLEN * G4];   // layer1 gate pre-acts
__device__ float g_HT[(size_t)2 * BATCH * HID];         // layer1 final hidden
__device__ __align__(16) __nv_bfloat16 g_Xb [(size_t)BATCH * TLEN * DIN];     // X bf16
__device__ __align__(16) __nv_bfloat16 g_W0b[2 * G4 * DIN];                   // Wih0 bf16
__device__ __align__(16) __nv_bfloat16 g_W1b[2 * G4 * 2 * HID];               // Wih1 bf16
__device__ __align__(16) __nv_bfloat16 g_H1b[(size_t)BATCH * TLEN * 2 * HID]; // layer0 out bf16

// ---------------------------------------------------------------------------
// fp32 -> bf16 elementwise convert (pairs)
// ---------------------------------------------------------------------------
__global__ __launch_bounds__(256)
void f2bf_kernel(const float* __restrict__ src, __nv_bfloat16* __restrict__ dst,
                 int n2)
{
    int i = blockIdx.x * 256 + threadIdx.x;
    if (i < n2) {
        float2 v = ((const float2*)src)[i];
        ((unsigned*)dst)[i] = pack_bf16(v.x, v.y);
    }
}

// ---------------------------------------------------------------------------
// Gate-input GEMM, bf16 inputs, cp.async 2-stage pipeline + ldmatrix ("NT"):
//   G[dir][b][t][g] = A[m][:] . W[n][:] + bias[n]     (A, W already bf16)
//   CTA tile 128x128, BK=32, 8 warps (4m x 2n), warp tile 32x64.
//   Smem rows padded to 40 b16 (80 B) -> bank-distinct ldmatrix phases.
//   M-tiles entirely past len[b] are skipped (values never read downstream).
// ---------------------------------------------------------------------------
template <int KDIM>
__global__ __launch_bounds__(256, 2)
void gate_gemm_bf16(const __nv_bfloat16* __restrict__ A,
                    const __nv_bfloat16* __restrict__ W,
                    const float* __restrict__ bias,
                    const int*   __restrict__ lens,
                    float*       __restrict__ G)
{
    constexpr int BM = 128, BN = 128, BK = 32, LD = 40;   // LD in b16 elems
    constexpr int NIT = KDIM / BK;
    __shared__ __align__(16) __nv_bfloat16 As[2][BM * LD];
    __shared__ __align__(16) __nv_bfloat16 Ws[2][BN * LD];

    const int m0 = blockIdx.y * BM;
    const int n0 = blockIdx.x * BN;
    const int b  = m0 >> 9;                 // 128 | 512 -> one batch per tile
    if ((m0 & 511) >= lens[b]) return;      // whole tile is padding

    const int tid  = threadIdx.x;
    const int lane = tid & 31;
    const int w    = tid >> 5;
    const int g    = lane >> 2;             // groupID
    const int t    = lane & 3;              // threadID in group
    const int wm   = w >> 1;                // m warp 0..3 (32 rows each)
    const int wn   = w & 1;                 // n warp 0..1 (64 cols each)

    // loader: thread covers 16 consecutive k (32 B) of one row via 2 cp.async
    const int lrow = tid >> 1;
    const int c16  = (tid & 1) * 16;
    const __nv_bfloat16* Agp = A + (size_t)(m0 + lrow) * KDIM + c16;
    const __nv_bfloat16* Wgp = W + (size_t)(n0 + lrow) * KDIM + c16;
    const unsigned sAb[2] = { smem_u32(&As[0][0]), smem_u32(&As[1][0]) };
    const unsigned sWb[2] = { smem_u32(&Ws[0][0]), smem_u32(&Ws[1][0]) };
    const unsigned soff   = (lrow * LD + c16) * 2;   // byte offset in tile

    // ldmatrix lane -> matrix/row decomposition (base-relative byte offsets)
    const int lq = lane >> 3;
    const int lr = lane & 7;
    const unsigned aoff0 = ((wm * 32 +      (lq & 1) * 8 + lr) * LD + (lq >> 1) * 8) * 2;
    const unsigned aoff1 = ((wm * 32 + 16 + (lq & 1) * 8 + lr) * LD + (lq >> 1) * 8) * 2;
    unsigned boff[4];
#pragma unroll
    for (int p = 0; p < 4; p++)
        boff[p] = ((wn * 64 + p * 16 + (lq & 1) * 8 + lr) * LD + (lq >> 1) * 8) * 2;

    float d[2][8][4];
#pragma unroll
    for (int mi = 0; mi < 2; mi++)
#pragma unroll
        for (int ni = 0; ni < 8; ni++)
#pragma unroll
            for (int c = 0; c < 4; c++) d[mi][ni][c] = 0.f;

    // prologue: issue stage 0
    {
        CP_ASYNC16(sAb[0] + soff,      Agp);
        CP_ASYNC16(sAb[0] + soff + 16, Agp + 8);
        CP_ASYNC16(sWb[0] + soff,      Wgp);
        CP_ASYNC16(sWb[0] + soff + 16, Wgp + 8);
        CP_COMMIT();
    }

#pragma unroll
    for (int it = 0; it < NIT; it++) {
        if (it + 1 < NIT) {   // issue next stage into the other buffer
            const int nb = (it + 1) & 1;
            const __nv_bfloat16* ag = Agp + (it + 1) * BK;
            const __nv_bfloat16* wg = Wgp + (it + 1) * BK;
            CP_ASYNC16(sAb[nb] + soff,      ag);
            CP_ASYNC16(sAb[nb] + soff + 16, ag + 8);
            CP_ASYNC16(sWb[nb] + soff,      wg);
            CP_ASYNC16(sWb[nb] + soff + 16, wg + 8);
            CP_COMMIT();
            asm volatile("cp.async.wait_group 1;");
        } else {
            asm volatile("cp.async.wait_group 0;");
        }
        __syncthreads();

        const unsigned bA = sAb[it & 1];
        const unsigned bW = sWb[it & 1];
#pragma unroll
        for (int kk = 0; kk < BK; kk += 16) {
            unsigned afr[2][4];
            ldsm_x4(afr[0], bA + aoff0 + kk * 2);
            ldsm_x4(afr[1], bA + aoff1 + kk * 2);
            unsigned bfr[8][2];
#pragma unroll
            for (int p = 0; p < 4; p++) {
                unsigned tmp[4];
                ldsm_x4(tmp, bW + boff[p] + kk * 2);
                bfr[2 * p][0]     = tmp[0];
                bfr[2 * p + 1][0] = tmp[1];
                bfr[2 * p][1]     = tmp[2];
                bfr[2 * p + 1][1] = tmp[3];
            }
#pragma unroll
            for (int ni = 0; ni < 8; ni++) {
                mma_bf16(d[0][ni], afr[0], bfr[ni][0], bfr[ni][1]);
                mma_bf16(d[1][ni], afr[1], bfr[ni][0], bfr[ni][1]);
            }
        }
        __syncthreads();
    }

    // epilogue: +bias, scatter to G[dir][b][t][g] as float2 (cols 2t, 2t+1)
#pragma unroll
    for (int ni = 0; ni < 8; ni++) {
        const int col  = n0 + wn * 64 + ni * 8 + 2 * t;
        const int dirn = col >> 9;
        const int gg   = col & 511;
        const float2 bv = *(const float2*)(bias + col);
#pragma unroll
        for (int mi = 0; mi < 2; mi++) {
            const int m  = m0 + wm * 32 + mi * 16 + g;
            const int tt = m & 511;
            const size_t base = ((((size_t)dirn * BATCH + b) * TLEN) + tt) * G4 + gg;
            float2 v0 = { d[mi][ni][0] + bv.x, d[mi][ni][1] + bv.y };
            float2 v1 = { d[mi][ni][2] + bv.x, d[mi][ni][3] + bv.y };
            *(float2*)&G[base]                  = v0;   // row m
            *(float2*)&G[base + 8 * (size_t)G4] = v1;   // row m+8
        }
    }
}

// ---------------------------------------------------------------------------
// Tensor-core LSTM recurrence (R12 structure, W fully in regs, acc-init fold).
//   One CTA = (dir, 8 batches) -> 64 CTAs; 512 threads = 16 warps.
//   Warp w owns units [8w,8w+8) x 4 gate types; pointwise register-local.
//   All 8 W k-steps in registers (64 regs); smem holds only the h-frag ring.
//   Gate inputs prefetched one step ahead and folded into the mma acc init.
//   h1 written as bf16 (GEMM1 consumes bf16 -> zero added error).
// ---------------------------------------------------------------------------
__global__ __launch_bounds__(512, 1)
void lstm_tc_kernel(const float* __restrict__ G,
                    const float* __restrict__ Whh,   // [2][512][128] fp32
                    const int*   __restrict__ lens,
                    __nv_bfloat16* __restrict__ h1,  // may be null (bf16 out)
                    float*       __restrict__ hT,    // may be null
                    int write_seq)
{
    __shared__ __align__(16) unsigned hfrag[2048];   // 2 buf x [ks][lane][4]

    const int tid  = threadIdx.x;
    const int lane = tid & 31;
    const int w    = tid >> 5;        // warp 0..15 -> units [8w, 8w+8)
    const int g    = lane >> 2;       // groupID == batch row (0..7)
    const int t    = lane & 3;        // threadID in group
    const int q0   = 8 * w + 2 * t;   // this lane's first unit

    const int dir = blockIdx.x >> 5;
    const int bb  = (blockIdx.x & 31) * 8;

    const float* Wd = Whh + (size_t)dir * G4 * HID;

    // ---- build W fragments, ALL in registers ----
    unsigned wreg[64];
#pragma unroll
    for (int ks = 0; ks < 8; ks++) {
#pragma unroll
        for (int gt = 0; gt < 4; gt++) {
            const float* row = Wd + (size_t)(gt * 128 + 8 * w + g) * HID + 16 * ks + 2 * t;
            float2 lo = *(const float2*)row;
            float2 hi = *(const float2*)(row + 8);
            wreg[(ks * 4 + gt) * 2]     = pack_bf16(lo.x, lo.y);
            wreg[(ks * 4 + gt) * 2 + 1] = pack_bf16(hi.x, hi.y);
        }
    }

    // zero both h-fragment buffers (rows 8-15 must stay zero forever)
    hfrag[tid]        = 0u;
    hfrag[tid + 512]  = 0u;
    hfrag[tid + 1024] = 0u;
    hfrag[tid + 1536] = 0u;

    const int len0 = lens[bb + g];        // this lane's batch
    int Tmax = 0;
#pragma unroll
    for (int i = 0; i < 8; i++) Tmax = max(Tmax, lens[bb + i]);

    const long long dstep = dir ? -(long long)G4 : (long long)G4;
    const float* p0 = G + (((size_t)(dir * BATCH + bb + g)) << 18)
                        + (size_t)(dir ? (len0 - 1) : 0) * G4;

    float c00 = 0.f, c01 = 0.f;
    float h00 = 0.f, h01 = 0.f;

    const int regA = (w & 1) ? 2 : 0;
    const int ksp  = w >> 1;

    __syncthreads();

    // prefetch gate inputs for step 0
    float2 gva[4];
#pragma unroll
    for (int gt = 0; gt < 4; gt++)
        gva[gt] = *(const float2*)(p0 + gt * 128 + q0);

    int cur = 0;
    for (int s = 0; s < Tmax; s++) {
        // advance pointer & prefetch step s+1 (hidden behind mma)
        if (s + 1 < len0) p0 += dstep;
        float2 gna[4];
#pragma unroll
        for (int gt = 0; gt < 4; gt++)
            gna[gt] = *(const float2*)(p0 + gt * 128 + q0);

        // acc init folds gate inputs (cols 0,1 = this lane's units; 2,3 unused)
        float acc[4][4];
#pragma unroll
        for (int gt = 0; gt < 4; gt++) {
            acc[gt][0] = gva[gt].x; acc[gt][1] = gva[gt].y;
            acc[gt][2] = 0.f;       acc[gt][3] = 0.f;
        }

        const unsigned hbase = cur * 1024;
#pragma unroll
        for (int ks = 0; ks < 8; ks++) {
            uint4 av = *(const uint4*)&hfrag[hbase + ks * 128 + lane * 4];
            unsigned a[4] = { av.x, av.y, av.z, av.w };
#pragma unroll
            for (int gt = 0; gt < 4; gt++)
                mma_bf16(acc[gt], a, wreg[(ks * 4 + gt) * 2],
                                     wreg[(ks * 4 + gt) * 2 + 1]);
        }

        // pointwise for batch bb+g (gate inputs already inside acc)
        if (s < len0) {
            c00 = fmaf(sigm_fast(acc[1][0]), c00,
                       sigm_fast(acc[0][0]) * tanh_fast(acc[2][0]));
            c01 = fmaf(sigm_fast(acc[1][1]), c01,
                       sigm_fast(acc[0][1]) * tanh_fast(acc[2][1]));
            h00 = sigm_fast(acc[3][0]) * tanh_fast(c00);
            h01 = sigm_fast(acc[3][1]) * tanh_fast(c01);
            if (write_seq) {
                const int tt = dir ? (len0 - 1 - s) : s;
                *(unsigned*)&h1[((size_t)(bb + g) * TLEN + tt) * (2 * HID)
                                + dir * HID + q0] = pack_bf16(h00, h01);
            }
        }

        // publish h (bf16x2) into the other buffer, A-frag row g
        hfrag[(cur ^ 1) * 1024 + ksp * 128 + lane * 4 + regA] = pack_bf16(h00, h01);
        __syncthreads();
        cur ^= 1;

#pragma unroll
        for (int gt = 0; gt < 4; gt++) gva[gt] = gna[gt];
    }

    if (hT)
        *(float2*)&hT[((size_t)(dir * BATCH + bb + g)) * HID + q0] = make_float2(h00, h01);

    if (write_seq) {
        // zero-fill padded region (reference masks hs to zero at t >= len)
        for (int qq = 0; qq < 8; qq++) {
            const int b  = bb + qq;
            const int lq = lens[b];
            const int ntail2 = (TLEN - lq) * 64;   // u32 units (2 bf16 each)
            for (int idx = tid; idx < ntail2; idx += 512) {
                const int tt = lq + (idx >> 6);
                const int kp = idx & 63;
                *(unsigned*)&h1[((size_t)b * TLEN + tt) * (2 * HID)
                                + dir * HID + kp * 2] = 0u;
            }
        }
    }
}

// ---------------------------------------------------------------------------
// FC + log_softmax.  h = concat([hT_backward, hT_forward]).
// ---------------------------------------------------------------------------
__global__ __launch_bounds__(32)
void fc_kernel(const float* __restrict__ HT,    // [2][256][128] (dir0=fwd, dir1=bwd)
               const float* __restrict__ Wfc,   // [12][256]
               const float* __restrict__ bfc,   // [12]
               float*       __restrict__ out)   // [256][12]
{
    const int b = blockIdx.x;
    const int c = threadIdx.x;
    float acc = 0.f;
    if (c < NCLS) {
        acc = bfc[c];
        const float* hb = HT + ((size_t)BATCH + b) * HID;  // backward (first half)
        const float* hf = HT + (size_t)b * HID;            // forward  (second half)
        const float* w  = Wfc + c * (2 * HID);
#pragma unroll 4
        for (int k = 0; k < HID; k++) acc = fmaf(w[k], hb[k], acc);
#pragma unroll 4
        for (int k = 0; k < HID; k++) acc = fmaf(w[HID + k], hf[k], acc);
    }
    float mx = (c < NCLS) ? acc : -3.4e38f;
#pragma unroll
    for (int o = 16; o; o >>= 1) mx = fmaxf(mx, __shfl_xor_sync(0xffffffffu, mx, o));
    float e = (c < NCLS) ? expf(acc - mx) : 0.f;
    float ssum = e;
#pragma unroll
    for (int o = 16; o; o >>= 1) ssum += __shfl_xor_sync(0xffffffffu, ssum, o);
    if (c < NCLS) out[b * NCLS + c] = acc - mx - logf(ssum);
}

// ---------------------------------------------------------------------------
// Launch
// ---------------------------------------------------------------------------
extern "C" void kernel_launch(void* const* d_in, const int* in_sizes, int n_in,
                              void* d_out, int out_size)
{
    const float* X    = (const float*)d_in[0];
    const int*   lens = (const int*)  d_in[1];
    const float* Wih0 = (const float*)d_in[2];
    const float* Whh0 = (const float*)d_in[3];
    const float* b0   = (const float*)d_in[4];
    const float* Wih1 = (const float*)d_in[5];
    const float* Whh1 = (const float*)d_in[6];
    const float* b1   = (const float*)d_in[7];
    const float* Wfc  = (const float*)d_in[8];
    const float* bfc  = (const float*)d_in[9];
    float* out = (float*)d_out;

    float *G0, *G1, *HT;
    __nv_bfloat16 *Xb, *W0b, *W1b, *H1b;
    cudaGetSymbolAddress((void**)&G0,  g_G0);
    cudaGetSymbolAddress((void**)&G1,  g_G1);
    cudaGetSymbolAddress((void**)&HT,  g_HT);
    cudaGetSymbolAddress((void**)&Xb,  g_Xb);
    cudaGetSymbolAddress((void**)&W0b, g_W0b);
    cudaGetSymbolAddress((void**)&W1b, g_W1b);
    cudaGetSymbolAddress((void**)&H1b, g_H1b);

    dim3 gemm_grid(1024 / 128, MROWS / 128);   // 8 n-tiles x 1024 m-tiles

    // one-time fp32 -> bf16 conversions (X and input-projection weights)
    f2bf_kernel<<<(BATCH * TLEN * DIN / 2 + 255) / 256, 256>>>(X, Xb, BATCH * TLEN * DIN / 2);
    f2bf_kernel<<<(2 * G4 * DIN / 2 + 255) / 256, 256>>>(Wih0, W0b, 2 * G4 * DIN / 2);
    f2bf_kernel<<<(2 * G4 * 2 * HID / 2 + 255) / 256, 256>>>(Wih1, W1b, 2 * G4 * 2 * HID / 2);

    // layer 0: input gates (bf16 TC, cp.async pipeline), recurrence -> H1 (bf16)
    gate_gemm_bf16<DIN><<<gemm_grid, 256>>>(Xb, W0b, b0, lens, G0);
    lstm_tc_kernel<<<64, 512>>>(G0, Whh0, lens, H1b, nullptr, 1);

    // layer 1: input gates over H1 (bf16), recurrence -> final hiddens
    gate_gemm_bf16<2 * HID><<<gemm_grid, 256>>>(H1b, W1b, b1, lens, G1);
    lstm_tc_kernel<<<64, 512>>>(G1, Whh1, lens, nullptr, HT, 0);

    // classifier head
    fc_kernel<<<BATCH, 32>>>(HT, Wfc, bfc, out);
}

// round 14
// speedup vs baseline: 1.7164x; 1.0088x over previous
#include <cuda_runtime.h>
#include <cuda_bf16.h>
#include <math.h>

// ---------------------------------------------------------------------------
// Problem constants
// ---------------------------------------------------------------------------
#define BATCH 256
#define TLEN  512
#define DIN   64
#define HID   128
#define G4    512              // 4*H
#define NCLS  12
#define MROWS (BATCH * TLEN)   // 131072

// ---- helpers ----
// pack two f32 -> bf16x2 (low = first arg)
__device__ __forceinline__ unsigned pack_bf16(float lo, float hi) {
    unsigned r;
    asm("cvt.rn.bf16x2.f32 %0, %1, %2;" : "=r"(r) : "f"(hi), "f"(lo));
    return r;
}
__device__ __forceinline__ void mma_bf16(float d[4], const unsigned a[4],
                                         unsigned b0, unsigned b1) {
    asm("mma.sync.aligned.m16n8k16.row.col.f32.bf16.bf16.f32 "
        "{%0,%1,%2,%3},{%4,%5,%6,%7},{%8,%9},{%0,%1,%2,%3};"
        : "+f"(d[0]), "+f"(d[1]), "+f"(d[2]), "+f"(d[3])
        : "r"(a[0]), "r"(a[1]), "r"(a[2]), "r"(a[3]), "r"(b0), "r"(b1));
}
__device__ __forceinline__ float tanh_fast(float x) {
    float y; asm("tanh.approx.f32 %0, %1;" : "=f"(y) : "f"(x)); return y;
}
__device__ __forceinline__ float sigm_fast(float x) {
    return fmaf(0.5f, tanh_fast(0.5f * x), 0.5f);
}
__device__ __forceinline__ unsigned smem_u32(const void* p) {
    unsigned a;
    asm("{ .reg .u64 t; cvta.to.shared.u64 t, %1; cvt.u32.u64 %0, t; }"
        : "=r"(a) : "l"(p));
    return a;
}
__device__ __forceinline__ void ldsm_x4(unsigned r[4], unsigned addr) {
    asm volatile("ldmatrix.sync.aligned.m8n8.x4.shared.b16 {%0,%1,%2,%3}, [%4];"
                 : "=r"(r[0]), "=r"(r[1]), "=r"(r[2]), "=r"(r[3]) : "r"(addr));
}
#define CP_ASYNC16(sm, gp) \
    asm volatile("cp.async.cg.shared.global [%0], [%1], 16;" :: "r"(sm), "l"(gp))
#define CP_COMMIT() asm volatile("cp.async.commit_group;")

// exact bf16x2 -> 2x fp32 (low, high)
__device__ __forceinline__ float bf_lo(unsigned u) { return __uint_as_float(u << 16); }
__device__ __forceinline__ float bf_hi(unsigned u) { return __uint_as_float(u & 0xffff0000u); }

// ---------------------------------------------------------------------------
// Scratch (device globals; allocation in kernel_launch is forbidden)
// ---------------------------------------------------------------------------
__device__ __align__(16) __nv_bfloat16 g_G0b[(size_t)2 * BATCH * TLEN * G4];  // layer0 gate pre-acts (bf16)
__device__ __align__(16) __nv_bfloat16 g_G1b[(size_t)2 * BATCH * TLEN * G4];  // layer1 gate pre-acts (bf16)
__device__ float g_HT[(size_t)2 * BATCH * HID];                               // layer1 final hidden
__device__ __align__(16) __nv_bfloat16 g_Xb [(size_t)BATCH * TLEN * DIN];     // X bf16
__device__ __align__(16) __nv_bfloat16 g_W0b[2 * G4 * DIN];                   // Wih0 bf16
__device__ __align__(16) __nv_bfloat16 g_W1b[2 * G4 * 2 * HID];               // Wih1 bf16
__device__ __align__(16) __nv_bfloat16 g_H1b[(size_t)BATCH * TLEN * 2 * HID]; // layer0 out bf16

// ---------------------------------------------------------------------------
// fp32 -> bf16 elementwise convert (pairs)
// ---------------------------------------------------------------------------
__global__ __launch_bounds__(256)
void f2bf_kernel(const float* __restrict__ src, __nv_bfloat16* __restrict__ dst,
                 int n2)
{
    int i = blockIdx.x * 256 + threadIdx.x;
    if (i < n2) {
        float2 v = ((const float2*)src)[i];
        ((unsigned*)dst)[i] = pack_bf16(v.x, v.y);
    }
}

// ---------------------------------------------------------------------------
// Gate-input GEMM, bf16 in/out, cp.async 2-stage pipeline + ldmatrix ("NT"):
//   G[dir][b][t][g] = bf16( A[m][:] . W[n][:] + bias[n] )
//   CTA tile 128x128, BK=32, 8 warps (4m x 2n), warp tile 32x64.
//   Smem rows padded to 40 b16 (80 B) -> bank-distinct ldmatrix phases.
//   M-tiles entirely past len[b] are skipped (values never read downstream).
// ---------------------------------------------------------------------------
template <int KDIM>
__global__ __launch_bounds__(256, 2)
void gate_gemm_bf16(const __nv_bfloat16* __restrict__ A,
                    const __nv_bfloat16* __restrict__ W,
                    const float* __restrict__ bias,
                    const int*   __restrict__ lens,
                    __nv_bfloat16* __restrict__ G)
{
    constexpr int BM = 128, BN = 128, BK = 32, LD = 40;   // LD in b16 elems
    constexpr int NIT = KDIM / BK;
    __shared__ __align__(16) __nv_bfloat16 As[2][BM * LD];
    __shared__ __align__(16) __nv_bfloat16 Ws[2][BN * LD];

    const int m0 = blockIdx.y * BM;
    const int n0 = blockIdx.x * BN;
    const int b  = m0 >> 9;                 // 128 | 512 -> one batch per tile
    if ((m0 & 511) >= lens[b]) return;      // whole tile is padding

    const int tid  = threadIdx.x;
    const int lane = tid & 31;
    const int w    = tid >> 5;
    const int g    = lane >> 2;             // groupID
    const int t    = lane & 3;              // threadID in group
    const int wm   = w >> 1;                // m warp 0..3 (32 rows each)
    const int wn   = w & 1;                 // n warp 0..1 (64 cols each)

    // loader: thread covers 16 consecutive k (32 B) of one row via 2 cp.async
    const int lrow = tid >> 1;
    const int c16  = (tid & 1) * 16;
    const __nv_bfloat16* Agp = A + (size_t)(m0 + lrow) * KDIM + c16;
    const __nv_bfloat16* Wgp = W + (size_t)(n0 + lrow) * KDIM + c16;
    const unsigned sAb[2] = { smem_u32(&As[0][0]), smem_u32(&As[1][0]) };
    const unsigned sWb[2] = { smem_u32(&Ws[0][0]), smem_u32(&Ws[1][0]) };
    const unsigned soff   = (lrow * LD + c16) * 2;   // byte offset in tile

    // ldmatrix lane -> matrix/row decomposition (base-relative byte offsets)
    const int lq = lane >> 3;
    const int lr = lane & 7;
    const unsigned aoff0 = ((wm * 32 +      (lq & 1) * 8 + lr) * LD + (lq >> 1) * 8) * 2;
    const unsigned aoff1 = ((wm * 32 + 16 + (lq & 1) * 8 + lr) * LD + (lq >> 1) * 8) * 2;
    unsigned boff[4];
#pragma unroll
    for (int p = 0; p < 4; p++)
        boff[p] = ((wn * 64 + p * 16 + (lq & 1) * 8 + lr) * LD + (lq >> 1) * 8) * 2;

    float d[2][8][4];
#pragma unroll
    for (int mi = 0; mi < 2; mi++)
#pragma unroll
        for (int ni = 0; ni < 8; ni++)
#pragma unroll
            for (int c = 0; c < 4; c++) d[mi][ni][c] = 0.f;

    // prologue: issue stage 0
    {
        CP_ASYNC16(sAb[0] + soff,      Agp);
        CP_ASYNC16(sAb[0] + soff + 16, Agp + 8);
        CP_ASYNC16(sWb[0] + soff,      Wgp);
        CP_ASYNC16(sWb[0] + soff + 16, Wgp + 8);
        CP_COMMIT();
    }

#pragma unroll
    for (int it = 0; it < NIT; it++) {
        if (it + 1 < NIT) {   // issue next stage into the other buffer
            const int nb = (it + 1) & 1;
            const __nv_bfloat16* ag = Agp + (it + 1) * BK;
            const __nv_bfloat16* wg = Wgp + (it + 1) * BK;
            CP_ASYNC16(sAb[nb] + soff,      ag);
            CP_ASYNC16(sAb[nb] + soff + 16, ag + 8);
            CP_ASYNC16(sWb[nb] + soff,      wg);
            CP_ASYNC16(sWb[nb] + soff + 16, wg + 8);
            CP_COMMIT();
            asm volatile("cp.async.wait_group 1;");
        } else {
            asm volatile("cp.async.wait_group 0;");
        }
        __syncthreads();

        const unsigned bA = sAb[it & 1];
        const unsigned bW = sWb[it & 1];
#pragma unroll
        for (int kk = 0; kk < BK; kk += 16) {
            unsigned afr[2][4];
            ldsm_x4(afr[0], bA + aoff0 + kk * 2);
            ldsm_x4(afr[1], bA + aoff1 + kk * 2);
            unsigned bfr[8][2];
#pragma unroll
            for (int p = 0; p < 4; p++) {
                unsigned tmp[4];
                ldsm_x4(tmp, bW + boff[p] + kk * 2);
                bfr[2 * p][0]     = tmp[0];
                bfr[2 * p + 1][0] = tmp[1];
                bfr[2 * p][1]     = tmp[2];
                bfr[2 * p + 1][1] = tmp[3];
            }
#pragma unroll
            for (int ni = 0; ni < 8; ni++) {
                mma_bf16(d[0][ni], afr[0], bfr[ni][0], bfr[ni][1]);
                mma_bf16(d[1][ni], afr[1], bfr[ni][0], bfr[ni][1]);
            }
        }
        __syncthreads();
    }

    // epilogue: +bias, pack bf16x2, scatter to G[dir][b][t][g] (cols 2t,2t+1)
#pragma unroll
    for (int ni = 0; ni < 8; ni++) {
        const int col  = n0 + wn * 64 + ni * 8 + 2 * t;
        const int dirn = col >> 9;
        const int gg   = col & 511;
        const float2 bv = *(const float2*)(bias + col);
#pragma unroll
        for (int mi = 0; mi < 2; mi++) {
            const int m  = m0 + wm * 32 + mi * 16 + g;
            const int tt = m & 511;
            const size_t base = ((((size_t)dirn * BATCH + b) * TLEN) + tt) * G4 + gg;
            *(unsigned*)&G[base] =
                pack_bf16(d[mi][ni][0] + bv.x, d[mi][ni][1] + bv.y);   // row m
            *(unsigned*)&G[base + 8 * (size_t)G4] =
                pack_bf16(d[mi][ni][2] + bv.x, d[mi][ni][3] + bv.y);   // row m+8
        }
    }
}

// ---------------------------------------------------------------------------
// Tensor-core LSTM recurrence (R13 structure; G now bf16).
//   One CTA = (dir, 8 batches) -> 64 CTAs; 512 threads = 16 warps.
//   Warp w owns units [8w,8w+8) x 4 gate types; pointwise register-local.
//   All 8 W k-steps in registers (64 regs); smem holds only the h-frag ring.
//   Gate inputs (bf16x2) prefetched one step ahead, unpacked exactly via
//   shift/mask, folded into the mma accumulator init.
//   h1 written as bf16 (GEMM1 consumes bf16 -> zero added error).
// ---------------------------------------------------------------------------
__global__ __launch_bounds__(512, 1)
void lstm_tc_kernel(const __nv_bfloat16* __restrict__ G,
                    const float* __restrict__ Whh,   // [2][512][128] fp32
                    const int*   __restrict__ lens,
                    __nv_bfloat16* __restrict__ h1,  // may be null (bf16 out)
                    float*       __restrict__ hT,    // may be null
                    int write_seq)
{
    __shared__ __align__(16) unsigned hfrag[2048];   // 2 buf x [ks][lane][4]

    const int tid  = threadIdx.x;
    const int lane = tid & 31;
    const int w    = tid >> 5;        // warp 0..15 -> units [8w, 8w+8)
    const int g    = lane >> 2;       // groupID == batch row (0..7)
    const int t    = lane & 3;        // threadID in group
    const int q0   = 8 * w + 2 * t;   // this lane's first unit

    const int dir = blockIdx.x >> 5;
    const int bb  = (blockIdx.x & 31) * 8;

    const float* Wd = Whh + (size_t)dir * G4 * HID;

    // ---- build W fragments, ALL in registers ----
    unsigned wreg[64];
#pragma unroll
    for (int ks = 0; ks < 8; ks++) {
#pragma unroll
        for (int gt = 0; gt < 4; gt++) {
            const float* row = Wd + (size_t)(gt * 128 + 8 * w + g) * HID + 16 * ks + 2 * t;
            float2 lo = *(const float2*)row;
            float2 hi = *(const float2*)(row + 8);
            wreg[(ks * 4 + gt) * 2]     = pack_bf16(lo.x, lo.y);
            wreg[(ks * 4 + gt) * 2 + 1] = pack_bf16(hi.x, hi.y);
        }
    }

    // zero both h-fragment buffers (rows 8-15 must stay zero forever)
    hfrag[tid]        = 0u;
    hfrag[tid + 512]  = 0u;
    hfrag[tid + 1024] = 0u;
    hfrag[tid + 1536] = 0u;

    const int len0 = lens[bb + g];        // this lane's batch
    int Tmax = 0;
#pragma unroll
    for (int i = 0; i < 8; i++) Tmax = max(Tmax, lens[bb + i]);

    const long long dstep = dir ? -(long long)G4 : (long long)G4;   // in bf16 elems
    const __nv_bfloat16* p0 = G + (((size_t)(dir * BATCH + bb + g)) << 18)
                                + (size_t)(dir ? (len0 - 1) : 0) * G4;

    float c00 = 0.f, c01 = 0.f;
    float h00 = 0.f, h01 = 0.f;

    const int regA = (w & 1) ? 2 : 0;
    const int ksp  = w >> 1;

    __syncthreads();

    // prefetch gate inputs for step 0 (bf16x2 per gate type)
    unsigned gvu[4];
#pragma unroll
    for (int gt = 0; gt < 4; gt++)
        gvu[gt] = *(const unsigned*)(p0 + gt * 128 + q0);

    int cur = 0;
    for (int s = 0; s < Tmax; s++) {
        // advance pointer & prefetch step s+1 (hidden behind mma)
        if (s + 1 < len0) p0 += dstep;
        unsigned gnu[4];
#pragma unroll
        for (int gt = 0; gt < 4; gt++)
            gnu[gt] = *(const unsigned*)(p0 + gt * 128 + q0);

        // acc init folds gate inputs (cols 0,1 = this lane's units; 2,3 unused)
        float acc[4][4];
#pragma unroll
        for (int gt = 0; gt < 4; gt++) {
            acc[gt][0] = bf_lo(gvu[gt]); acc[gt][1] = bf_hi(gvu[gt]);
            acc[gt][2] = 0.f;            acc[gt][3] = 0.f;
        }

        const unsigned hbase = cur * 1024;
#pragma unroll
        for (int ks = 0; ks < 8; ks++) {
            uint4 av = *(const uint4*)&hfrag[hbase + ks * 128 + lane * 4];
            unsigned a[4] = { av.x, av.y, av.z, av.w };
#pragma unroll
            for (int gt = 0; gt < 4; gt++)
                mma_bf16(acc[gt], a, wreg[(ks * 4 + gt) * 2],
                                     wreg[(ks * 4 + gt) * 2 + 1]);
        }

        // pointwise for batch bb+g (gate inputs already inside acc)
        if (s < len0) {
            c00 = fmaf(sigm_fast(acc[1][0]), c00,
                       sigm_fast(acc[0][0]) * tanh_fast(acc[2][0]));
            c01 = fmaf(sigm_fast(acc[1][1]), c01,
                       sigm_fast(acc[0][1]) * tanh_fast(acc[2][1]));
            h00 = sigm_fast(acc[3][0]) * tanh_fast(c00);
            h01 = sigm_fast(acc[3][1]) * tanh_fast(c01);
            if (write_seq) {
                const int tt = dir ? (len0 - 1 - s) : s;
                *(unsigned*)&h1[((size_t)(bb + g) * TLEN + tt) * (2 * HID)
                                + dir * HID + q0] = pack_bf16(h00, h01);
            }
        }

        // publish h (bf16x2) into the other buffer, A-frag row g
        hfrag[(cur ^ 1) * 1024 + ksp * 128 + lane * 4 + regA] = pack_bf16(h00, h01);
        __syncthreads();
        cur ^= 1;

#pragma unroll
        for (int gt = 0; gt < 4; gt++) gvu[gt] = gnu[gt];
    }

    if (hT)
        *(float2*)&hT[((size_t)(dir * BATCH + bb + g)) * HID + q0] = make_float2(h00, h01);

    if (write_seq) {
        // zero-fill padded region (reference masks hs to zero at t >= len)
        for (int qq = 0; qq < 8; qq++) {
            const int b  = bb + qq;
            const int lq = lens[b];
            const int ntail2 = (TLEN - lq) * 64;   // u32 units (2 bf16 each)
            for (int idx = tid; idx < ntail2; idx += 512) {
                const int tt = lq + (idx >> 6);
                const int kp = idx & 63;
                *(unsigned*)&h1[((size_t)b * TLEN + tt) * (2 * HID)
                                + dir * HID + kp * 2] = 0u;
            }
        }
    }
}

// ---------------------------------------------------------------------------
// FC + log_softmax.  h = concat([hT_backward, hT_forward]).
// ---------------------------------------------------------------------------
__global__ __launch_bounds__(32)
void fc_kernel(const float* __restrict__ HT,    // [2][256][128] (dir0=fwd, dir1=bwd)
               const float* __restrict__ Wfc,   // [12][256]
               const float* __restrict__ bfc,   // [12]
               float*       __restrict__ out)   // [256][12]
{
    const int b = blockIdx.x;
    const int c = threadIdx.x;
    float acc = 0.f;
    if (c < NCLS) {
        acc = bfc[c];
        const float* hb = HT + ((size_t)BATCH + b) * HID;  // backward (first half)
        const float* hf = HT + (size_t)b * HID;            // forward  (second half)
        const float* w  = Wfc + c * (2 * HID);
#pragma unroll 4
        for (int k = 0; k < HID; k++) acc = fmaf(w[k], hb[k], acc);
#pragma unroll 4
        for (int k = 0; k < HID; k++) acc = fmaf(w[HID + k], hf[k], acc);
    }
    float mx = (c < NCLS) ? acc : -3.4e38f;
#pragma unroll
    for (int o = 16; o; o >>= 1) mx = fmaxf(mx, __shfl_xor_sync(0xffffffffu, mx, o));
    float e = (c < NCLS) ? expf(acc - mx) : 0.f;
    float ssum = e;
#pragma unroll
    for (int o = 16; o; o >>= 1) ssum += __shfl_xor_sync(0xffffffffu, ssum, o);
    if (c < NCLS) out[b * NCLS + c] = acc - mx - logf(ssum);
}

// ---------------------------------------------------------------------------
// Launch
// ---------------------------------------------------------------------------
extern "C" void kernel_launch(void* const* d_in, const int* in_sizes, int n_in,
                              void* d_out, int out_size)
{
    const float* X    = (const float*)d_in[0];
    const int*   lens = (const int*)  d_in[1];
    const float* Wih0 = (const float*)d_in[2];
    const float* Whh0 = (const float*)d_in[3];
    const float* b0   = (const float*)d_in[4];
    const float* Wih1 = (const float*)d_in[5];
    const float* Whh1 = (const float*)d_in[6];
    const float* b1   = (const float*)d_in[7];
    const float* Wfc  = (const float*)d_in[8];
    const float* bfc  = (const float*)d_in[9];
    float* out = (float*)d_out;

    float *HT;
    __nv_bfloat16 *G0b, *G1b, *Xb, *W0b, *W1b, *H1b;
    cudaGetSymbolAddress((void**)&G0b, g_G0b);
    cudaGetSymbolAddress((void**)&G1b, g_G1b);
    cudaGetSymbolAddress((void**)&HT,  g_HT);
    cudaGetSymbolAddress((void**)&Xb,  g_Xb);
    cudaGetSymbolAddress((void**)&W0b, g_W0b);
    cudaGetSymbolAddress((void**)&W1b, g_W1b);
    cudaGetSymbolAddress((void**)&H1b, g_H1b);

    dim3 gemm_grid(1024 / 128, MROWS / 128);   // 8 n-tiles x 1024 m-tiles

    // one-time fp32 -> bf16 conversions (X and input-projection weights)
    f2bf_kernel<<<(BATCH * TLEN * DIN / 2 + 255) / 256, 256>>>(X, Xb, BATCH * TLEN * DIN / 2);
    f2bf_kernel<<<(2 * G4 * DIN / 2 + 255) / 256, 256>>>(Wih0, W0b, 2 * G4 * DIN / 2);
    f2bf_kernel<<<(2 * G4 * 2 * HID / 2 + 255) / 256, 256>>>(Wih1, W1b, 2 * G4 * 2 * HID / 2);

    // layer 0: input gates (bf16 TC, cp.async), recurrence -> H1 (bf16)
    gate_gemm_bf16<DIN><<<gemm_grid, 256>>>(Xb, W0b, b0, lens, G0b);
    lstm_tc_kernel<<<64, 512>>>(G0b, Whh0, lens, H1b, nullptr, 1);

    // layer 1: input gates over H1 (bf16), recurrence -> final hiddens
    gate_gemm_bf16<2 * HID><<<gemm_grid, 256>>>(H1b, W1b, b1, lens, G1b);
    lstm_tc_kernel<<<64, 512>>>(G1b, Whh1, lens, nullptr, HT, 0);

    // classifier head
    fc_kernel<<<BATCH, 32>>>(HT, Wfc, bfc, out);
}